// round 1
// baseline (speedup 1.0000x reference)
#include <cuda_runtime.h>
#include <math.h>

// Problem constants (fixed shapes from reference)
#define B_    8
#define N_    512
#define D_    1024
#define H_    16
#define HD_   64
#define NI_   4
#define G_    2
#define MROWS (B_*N_)      // 4096
#define SEQ   (NI_*N_)     // 2048
#define GH    (G_*H_)      // 32
#define SCALE 0.125f       // HD^-0.5
#define S2    0.0078125f   // SCALE / H

// ---------------- scratch (device globals; no allocation allowed) ------------
static __device__ float g_qp[MROWS*D_];
static __device__ float g_kp[MROWS*D_];
static __device__ float g_vp[MROWS*D_];
static __device__ float g_qs[GH*SEQ*HD_];
static __device__ float g_ks[GH*SEQ*HD_];
static __device__ float g_vs[GH*SEQ*HD_];
static __device__ float g_attn[MROWS*D_];
static __device__ float g_feat[MROWS*D_];
static __device__ float g_iq[MROWS*D_];
static __device__ float g_ik[MROWS*D_];
static __device__ float g_gacc[MROWS];

// ---------------- generic SGEMM: C = (rowscale .* A) @ W + bias --------------
// A row-major [M,K], W row-major [K,N]. M%128==0, N%128==0, K%8==0.
// rowAcc != nullptr: scale A row r by (1 + rowAcc[r]/512).
__global__ __launch_bounds__(256) void sgemm_bias_kernel(
    const float* __restrict__ A, const float* __restrict__ W,
    const float* __restrict__ bias, float* __restrict__ C,
    int M, int N, int K, const float* __restrict__ rowAcc)
{
    const int BK = 8;
    __shared__ float As[BK][128];
    __shared__ float Bs[BK][128];

    int tid  = threadIdx.x;
    int brow = blockIdx.y * 128;
    int bcol = blockIdx.x * 128;

    int aRow = tid >> 1;          // 0..127
    int aCol = (tid & 1) * 4;     // 0 or 4
    int bRow = tid >> 5;          // 0..7
    int bCol = (tid & 31) * 4;    // 0..124

    int tRow = (tid >> 4) * 8;
    int tCol = (tid & 15) * 8;

    float acc[8][8];
#pragma unroll
    for (int i = 0; i < 8; i++)
#pragma unroll
        for (int j = 0; j < 8; j++) acc[i][j] = 0.f;

    float scale = 1.0f;
    if (rowAcc) scale = 1.0f + rowAcc[brow + aRow] * (1.0f/512.0f);

    const float* Aptr = A + (long)(brow + aRow) * K + aCol;
    const float* Bptr = W + (long)bRow * N + bcol + bCol;

    for (int k0 = 0; k0 < K; k0 += BK) {
        float4 av = *(const float4*)(Aptr + k0);
        As[aCol+0][aRow] = av.x * scale;
        As[aCol+1][aRow] = av.y * scale;
        As[aCol+2][aRow] = av.z * scale;
        As[aCol+3][aRow] = av.w * scale;
        float4 bv = *(const float4*)(Bptr + (long)k0 * N);
        *(float4*)&Bs[bRow][bCol] = bv;
        __syncthreads();
#pragma unroll
        for (int k = 0; k < BK; k++) {
            float ra[8], rb[8];
#pragma unroll
            for (int i = 0; i < 8; i++) ra[i] = As[k][tRow + i];
#pragma unroll
            for (int j = 0; j < 8; j++) rb[j] = Bs[k][tCol + j];
#pragma unroll
            for (int i = 0; i < 8; i++)
#pragma unroll
                for (int j = 0; j < 8; j++)
                    acc[i][j] = fmaf(ra[i], rb[j], acc[i][j]);
        }
        __syncthreads();
    }

#pragma unroll
    for (int i = 0; i < 8; i++) {
        long r = brow + tRow + i;
        float* cp = C + r * (long)N + bcol + tCol;
#pragma unroll
        for (int j = 0; j < 8; j += 4) {
            float4 o;
            o.x = acc[i][j+0] + bias[bcol + tCol + j + 0];
            o.y = acc[i][j+1] + bias[bcol + tCol + j + 1];
            o.z = acc[i][j+2] + bias[bcol + tCol + j + 2];
            o.w = acc[i][j+3] + bias[bcol + tCol + j + 3];
            *(float4*)(cp + j) = o;
        }
    }
}

// ------------- RMS-norm (q,k) + scatter q/k/v into [GH, SEQ, HD] -------------
__global__ __launch_bounds__(256) void rms_scatter_kernel(
    const float* __restrict__ qp, const float* __restrict__ kp,
    const float* __restrict__ vp,
    const float* __restrict__ qw, const float* __restrict__ kw,
    float* __restrict__ qs, float* __restrict__ ks, float* __restrict__ vs)
{
    int wid  = (blockIdx.x * 256 + threadIdx.x) >> 5;   // [0, 65536)
    int lane = threadIdx.x & 31;
    int h  = wid & 15;
    int bn = wid >> 4;              // b*512 + n
    int b  = bn >> 9, n = bn & 511;
    long ibase = (long)bn * D_ + h * HD_;
    int g = b >> 2, inst = b & 3;
    long obase = (((long)(g*16 + h)) * SEQ + inst*512 + n) * HD_;

    // q: RMS norm
    {
        float v0 = qp[ibase + lane], v1 = qp[ibase + lane + 32];
        float ss = v0*v0 + v1*v1;
#pragma unroll
        for (int off = 16; off; off >>= 1) ss += __shfl_xor_sync(0xffffffffu, ss, off);
        float sc = rsqrtf(ss * (1.0f/64.0f) + 1e-6f);
        qs[obase + lane]      = v0 * sc * qw[lane];
        qs[obase + lane + 32] = v1 * sc * qw[lane + 32];
    }
    // k: RMS norm
    {
        float v0 = kp[ibase + lane], v1 = kp[ibase + lane + 32];
        float ss = v0*v0 + v1*v1;
#pragma unroll
        for (int off = 16; off; off >>= 1) ss += __shfl_xor_sync(0xffffffffu, ss, off);
        float sc = rsqrtf(ss * (1.0f/64.0f) + 1e-6f);
        ks[obase + lane]      = v0 * sc * kw[lane];
        ks[obase + lane + 32] = v1 * sc * kw[lane + 32];
    }
    // v: copy/scatter
    vs[obase + lane]      = vp[ibase + lane];
    vs[obase + lane + 32] = vp[ibase + lane + 32];
}

// ---------------- flash attention: 32 problems of 2048x2048x64 ---------------
// grid (32 q-tiles, 32 gh), 256 threads. Output written to [B*N, D] layout.
#define FLASH_SMEM ((3*64*65 + 64*64) * 4)
__global__ __launch_bounds__(256) void flash_kernel(
    const float* __restrict__ Qg, const float* __restrict__ Kg,
    const float* __restrict__ Vg, float* __restrict__ Out)
{
    extern __shared__ float sm[];
    float* Qs = sm;                 // 64 x 65
    float* Ks = Qs + 64*65;         // 64 x 65
    float* Ps = Ks + 64*65;         // 64 x 65
    float* Vs = Ps + 64*65;         // 64 x 64

    int tid = threadIdx.x;
    int qt  = blockIdx.x;           // 0..31
    int gh  = blockIdx.y;           // 0..31
    const float* Qbase = Qg + ((long)gh * SEQ + qt*64) * HD_;
    const float* Kb    = Kg + (long)gh * SEQ * HD_;
    const float* Vb    = Vg + (long)gh * SEQ * HD_;

    // load Q (pre-scaled by SCALE)
#pragma unroll
    for (int u = tid; u < 1024; u += 256) {
        int row = u >> 4; int c4 = (u & 15) << 2;
        float4 v = *(const float4*)(Qbase + row*64 + c4);
        float* d = Qs + row*65 + c4;
        d[0] = v.x*SCALE; d[1] = v.y*SCALE; d[2] = v.z*SCALE; d[3] = v.w*SCALE;
    }

    int ty = tid >> 4, tx = tid & 15;
    int row0 = ty * 4;
    float acc[4][4];
    float mi[4], li[4];
#pragma unroll
    for (int i = 0; i < 4; i++) {
        mi[i] = -1e30f; li[i] = 0.f;
#pragma unroll
        for (int j = 0; j < 4; j++) acc[i][j] = 0.f;
    }

    for (int kt = 0; kt < 32; kt++) {
        __syncthreads();   // prev-iter P/V consumers done before overwrite
#pragma unroll
        for (int u = tid; u < 1024; u += 256) {
            int row = u >> 4; int c4 = (u & 15) << 2;
            float4 kv = *(const float4*)(Kb + (long)(kt*64 + row)*64 + c4);
            float* d = Ks + row*65 + c4;
            d[0]=kv.x; d[1]=kv.y; d[2]=kv.z; d[3]=kv.w;
            float4 vv = *(const float4*)(Vb + (long)(kt*64 + row)*64 + c4);
            *(float4*)(Vs + row*64 + c4) = vv;
        }
        __syncthreads();

        // S = Qs @ Ks^T  (thread owns rows row0..row0+3, cols tx+16j)
        float s[4][4];
#pragma unroll
        for (int i = 0; i < 4; i++)
#pragma unroll
            for (int j = 0; j < 4; j++) s[i][j] = 0.f;
#pragma unroll 4
        for (int d = 0; d < 64; d++) {
            float rq[4], rk[4];
#pragma unroll
            for (int i = 0; i < 4; i++) rq[i] = Qs[(row0+i)*65 + d];
#pragma unroll
            for (int j = 0; j < 4; j++) rk[j] = Ks[(tx + 16*j)*65 + d];
#pragma unroll
            for (int i = 0; i < 4; i++)
#pragma unroll
                for (int j = 0; j < 4; j++)
                    s[i][j] = fmaf(rq[i], rk[j], s[i][j]);
        }

        // online softmax update, write P
#pragma unroll
        for (int i = 0; i < 4; i++) {
            float tm = fmaxf(fmaxf(s[i][0], s[i][1]), fmaxf(s[i][2], s[i][3]));
#pragma unroll
            for (int off = 8; off; off >>= 1)
                tm = fmaxf(tm, __shfl_xor_sync(0xffffffffu, tm, off, 16));
            float mnew = fmaxf(mi[i], tm);
            float corr = __expf(mi[i] - mnew);
            li[i] *= corr;
#pragma unroll
            for (int j = 0; j < 4; j++) acc[i][j] *= corr;
            mi[i] = mnew;
            float rs = 0.f;
#pragma unroll
            for (int j = 0; j < 4; j++) {
                float p = __expf(s[i][j] - mnew);
                Ps[(row0+i)*65 + tx + 16*j] = p;
                rs += p;
            }
#pragma unroll
            for (int off = 8; off; off >>= 1)
                rs += __shfl_xor_sync(0xffffffffu, rs, off, 16);
            li[i] += rs;
        }
        __syncthreads();

        // O += P @ V
#pragma unroll 4
        for (int kk = 0; kk < 64; kk++) {
            float rp[4], rv[4];
#pragma unroll
            for (int i = 0; i < 4; i++) rp[i] = Ps[(row0+i)*65 + kk];
#pragma unroll
            for (int j = 0; j < 4; j++) rv[j] = Vs[kk*64 + tx + 16*j];
#pragma unroll
            for (int i = 0; i < 4; i++)
#pragma unroll
                for (int j = 0; j < 4; j++)
                    acc[i][j] = fmaf(rp[i], rv[j], acc[i][j]);
        }
    }

    // epilogue: normalize, scatter to [B*N, D]
    int g = gh >> 4, h = gh & 15;
#pragma unroll
    for (int i = 0; i < 4; i++) {
        int r = qt*64 + row0 + i;            // within SEQ
        int inst = r >> 9, n = r & 511;
        int b = g*4 + inst;
        float inv = 1.0f / li[i];
        float* orow = Out + ((long)(b*512 + n)) * D_ + h * HD_;
#pragma unroll
        for (int j = 0; j < 4; j++)
            orow[tx + 16*j] = acc[i][j] * inv;
    }
}

// ---------------- instance feature: feat = mask @ embed[:4] ------------------
__global__ __launch_bounds__(256) void feat_kernel(
    const float* __restrict__ mask, const float* __restrict__ embed,
    float* __restrict__ feat)
{
    int row = blockIdx.x;   // 0..4095
    float m0 = mask[row*4+0], m1 = mask[row*4+1];
    float m2 = mask[row*4+2], m3 = mask[row*4+3];
    for (int c = threadIdx.x; c < D_; c += 256)
        feat[(long)row*D_ + c] = m0*embed[c] + m1*embed[D_ + c]
                               + m2*embed[2*D_ + c] + m3*embed[3*D_ + c];
}

// ---------------- zero the gate accumulator ----------------------------------
__global__ void zero_kernel(float* __restrict__ p, int n)
{
    int i = blockIdx.x * blockDim.x + threadIdx.x;
    if (i < n) p[i] = 0.f;
}

// --------- gate GEMM: per batch S = iq @ ik^T, fused sigmoid row-sum ---------
// grid (8 col-tiles, 8 row-tiles, 8 batches), 256 threads, 64x64 C tile.
__global__ __launch_bounds__(256) void gate_gemm_kernel(
    const float* __restrict__ IQ, const float* __restrict__ IK,
    float* __restrict__ gacc)
{
    __shared__ float As[64][17];
    __shared__ float Bs[64][17];
    int b = blockIdx.z;
    const float* A  = IQ + (long)b*512*D_ + (long)blockIdx.y*64*D_;
    const float* Bm = IK + (long)b*512*D_ + (long)blockIdx.x*64*D_;
    int tid = threadIdx.x, ty = tid >> 4, tx = tid & 15;
    int row0 = ty * 4;
    int lr = tid >> 2, lc4 = (tid & 3) * 4;   // load mapping: 64 rows x 16 cols

    float acc[4][4];
#pragma unroll
    for (int i = 0; i < 4; i++)
#pragma unroll
        for (int j = 0; j < 4; j++) acc[i][j] = 0.f;

    for (int k0 = 0; k0 < D_; k0 += 16) {
        __syncthreads();
        float4 av = *(const float4*)(A  + (long)lr*D_ + k0 + lc4);
        As[lr][lc4+0]=av.x; As[lr][lc4+1]=av.y; As[lr][lc4+2]=av.z; As[lr][lc4+3]=av.w;
        float4 bv = *(const float4*)(Bm + (long)lr*D_ + k0 + lc4);
        Bs[lr][lc4+0]=bv.x; Bs[lr][lc4+1]=bv.y; Bs[lr][lc4+2]=bv.z; Bs[lr][lc4+3]=bv.w;
        __syncthreads();
#pragma unroll
        for (int kk = 0; kk < 16; kk++) {
            float rq[4], rk[4];
#pragma unroll
            for (int i = 0; i < 4; i++) rq[i] = As[row0+i][kk];
#pragma unroll
            for (int j = 0; j < 4; j++) rk[j] = Bs[tx + 16*j][kk];
#pragma unroll
            for (int i = 0; i < 4; i++)
#pragma unroll
                for (int j = 0; j < 4; j++)
                    acc[i][j] = fmaf(rq[i], rk[j], acc[i][j]);
        }
    }

#pragma unroll
    for (int i = 0; i < 4; i++) {
        float rs = 0.f;
#pragma unroll
        for (int j = 0; j < 4; j++) {
            float x = acc[i][j] * S2;
            rs += 1.0f / (1.0f + __expf(-x));
        }
#pragma unroll
        for (int off = 8; off; off >>= 1)
            rs += __shfl_xor_sync(0xffffffffu, rs, off, 16);
        if (tx == 0)
            atomicAdd(&gacc[b*512 + blockIdx.y*64 + row0 + i], rs);
    }
}

// ------------------------------- launch --------------------------------------
extern "C" void kernel_launch(void* const* d_in, const int* in_sizes, int n_in,
                              void* d_out, int out_size)
{
    const float* x     = (const float*)d_in[0];
    const float* mask  = (const float*)d_in[1];
    const float* Wq    = (const float*)d_in[2];
    const float* bq    = (const float*)d_in[3];
    const float* Wk    = (const float*)d_in[4];
    const float* bk    = (const float*)d_in[5];
    const float* Wv    = (const float*)d_in[6];
    const float* bv    = (const float*)d_in[7];
    const float* Wo    = (const float*)d_in[8];
    const float* bo    = (const float*)d_in[9];
    const float* Wiq   = (const float*)d_in[10];
    const float* biq   = (const float*)d_in[11];
    const float* Wik   = (const float*)d_in[12];
    const float* bik   = (const float*)d_in[13];
    const float* embed = (const float*)d_in[14];
    const float* qw    = (const float*)d_in[15];
    const float* kw    = (const float*)d_in[16];
    float* out = (float*)d_out;

    float *qp, *kp, *vp, *qs, *ks, *vs, *attn, *feat, *iq, *ik, *gacc;
    cudaGetSymbolAddress((void**)&qp,   g_qp);
    cudaGetSymbolAddress((void**)&kp,   g_kp);
    cudaGetSymbolAddress((void**)&vp,   g_vp);
    cudaGetSymbolAddress((void**)&qs,   g_qs);
    cudaGetSymbolAddress((void**)&ks,   g_ks);
    cudaGetSymbolAddress((void**)&vs,   g_vs);
    cudaGetSymbolAddress((void**)&attn, g_attn);
    cudaGetSymbolAddress((void**)&feat, g_feat);
    cudaGetSymbolAddress((void**)&iq,   g_iq);
    cudaGetSymbolAddress((void**)&ik,   g_ik);
    cudaGetSymbolAddress((void**)&gacc, g_gacc);

    cudaFuncSetAttribute((const void*)flash_kernel,
                         cudaFuncAttributeMaxDynamicSharedMemorySize, FLASH_SMEM);

    dim3 gemm_grid(D_/128, MROWS/128);  // (8, 32)

    // QKV projections
    sgemm_bias_kernel<<<gemm_grid, 256>>>(x, Wq, bq, qp, MROWS, D_, D_, nullptr);
    sgemm_bias_kernel<<<gemm_grid, 256>>>(x, Wk, bk, kp, MROWS, D_, D_, nullptr);
    sgemm_bias_kernel<<<gemm_grid, 256>>>(x, Wv, bv, vp, MROWS, D_, D_, nullptr);

    // per-head RMS norm (q,k) + scatter to grouped layout
    rms_scatter_kernel<<<(MROWS*H_)/8, 256>>>(qp, kp, vp, qw, kw, qs, ks, vs);

    // grouped flash attention -> attn [B*N, D]
    flash_kernel<<<dim3(SEQ/64, GH), 256, FLASH_SMEM>>>(qs, ks, vs, attn);

    // instance features
    feat_kernel<<<MROWS, 256>>>(mask, embed, feat);

    // iq / ik projections
    sgemm_bias_kernel<<<gemm_grid, 256>>>(attn, Wiq, biq, iq, MROWS, D_, D_, nullptr);
    sgemm_bias_kernel<<<gemm_grid, 256>>>(feat, Wik, bik, ik, MROWS, D_, D_, nullptr);

    // gate: sum_m sigmoid((iq . ik) * S2)
    zero_kernel<<<(MROWS+255)/256, 256>>>(gacc, MROWS);
    gate_gemm_kernel<<<dim3(8, 8, 8), 256>>>(iq, ik, gacc);

    // final: out = (attn * (1 + gacc/512)) @ Wo + bo
    sgemm_bias_kernel<<<gemm_grid, 256>>>(attn, Wo, bo, out, MROWS, D_, D_, gacc);
}

// round 3
// speedup vs baseline: 1.5935x; 1.5935x over previous
#include <cuda_runtime.h>
#include <cuda_bf16.h>
#include <math.h>
#include <stdint.h>

// Problem constants
#define B_    8
#define N_    512
#define D_    1024
#define H_    16
#define HD_   64
#define NI_   4
#define G_    2
#define MROWS (B_*N_)      // 4096
#define SEQ   (NI_*N_)     // 2048
#define GH    (G_*H_)      // 32
#define SCALE 0.125f
#define S2    0.0078125f   // SCALE / H

// ---------------- scratch (device globals) -----------------------------------
static __device__ float g_qp[MROWS*D_];
static __device__ float g_kp[MROWS*D_];
static __device__ float g_vp[MROWS*D_];
static __device__ float g_qs[GH*SEQ*HD_];
static __device__ float g_ks[GH*SEQ*HD_];
static __device__ float g_vs[GH*SEQ*HD_];
static __device__ float g_attn[MROWS*D_];
static __device__ float g_feat[MROWS*D_];
static __device__ float g_iq[MROWS*D_];
static __device__ float g_ik[MROWS*D_];
static __device__ float g_gacc[MROWS];
static __device__ float g_scores[B_*N_*N_];   // 8 x 512 x 512

// split-bf16 weight (transposed [N,K]) and activation buffers
static __device__ __align__(256) __nv_bfloat16 g_wqh[D_*D_], g_wql[D_*D_];
static __device__ __align__(256) __nv_bfloat16 g_wkh[D_*D_], g_wkl[D_*D_];
static __device__ __align__(256) __nv_bfloat16 g_wvh[D_*D_], g_wvl[D_*D_];
static __device__ __align__(256) __nv_bfloat16 g_wiqh[D_*D_], g_wiql[D_*D_];
static __device__ __align__(256) __nv_bfloat16 g_wikh[D_*D_], g_wikl[D_*D_];
static __device__ __align__(256) __nv_bfloat16 g_woh[D_*D_], g_wol[D_*D_];
static __device__ __align__(256) __nv_bfloat16 g_xh[MROWS*D_],  g_xl[MROWS*D_];
static __device__ __align__(256) __nv_bfloat16 g_ah[MROWS*D_],  g_al[MROWS*D_];
static __device__ __align__(256) __nv_bfloat16 g_fh[MROWS*D_],  g_fl[MROWS*D_];
static __device__ __align__(256) __nv_bfloat16 g_iqh[MROWS*D_], g_iql[MROWS*D_];
static __device__ __align__(256) __nv_bfloat16 g_ikh[MROWS*D_], g_ikl[MROWS*D_];
static __device__ __align__(256) __nv_bfloat16 g_gth[MROWS*D_], g_gtl[MROWS*D_];

// ---------------- PTX helpers --------------------------------------------------
__device__ __forceinline__ uint32_t smem_u32(const void* p) {
    uint32_t a;
    asm("{ .reg .u64 t; cvta.to.shared.u64 t, %1; cvt.u32.u64 %0, t; }"
        : "=r"(a) : "l"(p));
    return a;
}

#define LDSM4(r, addr) \
    asm volatile("ldmatrix.sync.aligned.m8n8.x4.shared.b16 {%0,%1,%2,%3}, [%4];" \
        : "=r"((r)[0]), "=r"((r)[1]), "=r"((r)[2]), "=r"((r)[3]) : "r"(addr))

#define MMA16816(d, a, bv0, bv1) \
    asm volatile("mma.sync.aligned.m16n8k16.row.col.f32.bf16.bf16.f32 " \
        "{%0,%1,%2,%3}, {%4,%5,%6,%7}, {%8,%9}, {%0,%1,%2,%3};" \
        : "+f"((d)[0]), "+f"((d)[1]), "+f"((d)[2]), "+f"((d)[3]) \
        : "r"((a)[0]), "r"((a)[1]), "r"((a)[2]), "r"((a)[3]), "r"(bv0), "r"(bv1))

#define CP_ASYNC16(dst, src) \
    asm volatile("cp.async.cg.shared.global [%0], [%1], 16;" \
        :: "r"(dst), "l"(__cvta_generic_to_global(src)) : "memory")
#define CP_COMMIT() asm volatile("cp.async.commit_group;" ::: "memory")
#define CP_WAIT(n)  asm volatile("cp.async.wait_group %0;" :: "n"(n) : "memory")

// ---------------- HMMA split-bf16 GEMM ----------------------------------------
// C[z] = A[z] @ B[z]^T + bias.  A: [M,K] bf16 hi/lo, B: [N,K] bf16 hi/lo.
// CTA tile 128x128, BK=64, cp.async double buffer, 8 warps x (64x32).
// three_pass: 1 -> AhBh + AhBl + AlBh ; 0 -> AhBh only.
#define TC_SMEM (2*4*16384)   // 131072
__global__ __launch_bounds__(256, 1)
void mma_gemm_kernel(const __nv_bfloat16* __restrict__ Ahp, const __nv_bfloat16* __restrict__ Alp,
                     const __nv_bfloat16* __restrict__ Bhp, const __nv_bfloat16* __restrict__ Blp,
                     const float* __restrict__ bias, float* __restrict__ C,
                     int M, int N, int K, long sA, long sB, long sC, int three_pass)
{
    extern __shared__ char smem[];
    uint32_t sb = smem_u32(smem);
    int tid = threadIdx.x, wid = tid >> 5, lane = tid & 31;
    int m0 = blockIdx.y * 128, n0 = blockIdx.x * 128;
    long zb = blockIdx.z;
    const __nv_bfloat16* Ah = Ahp + zb * sA;
    const __nv_bfloat16* Al = Alp + zb * sA;
    const __nv_bfloat16* Bh = Bhp + zb * sB;
    const __nv_bfloat16* Bl = Blp + zb * sB;

    const int nsteps = K / 64;

    // issue one 64-deep k stage (4 tiles of 128 rows x 128B) via cp.async
    auto issue = [&](int step, int stage) {
        uint32_t stb = sb + stage * 65536;
        int k0 = step * 64;
#pragma unroll
        for (int i = 0; i < 16; i++) {
            int c = i * 256 + tid;
            int tile = c >> 10;          // 0=Ah 1=Al 2=Bh 3=Bl
            int w = c & 1023;
            int row = w >> 3, ch = w & 7;
            const __nv_bfloat16* src;
            int gr;
            if      (tile == 0) { src = Ah; gr = m0 + row; }
            else if (tile == 1) { src = Al; gr = m0 + row; }
            else if (tile == 2) { src = Bh; gr = n0 + row; }
            else                { src = Bl; gr = n0 + row; }
            const __nv_bfloat16* gp = src + (long)gr * K + k0 + ch * 8;
            uint32_t dst = stb + tile * 16384 + row * 128 + ((ch ^ (row & 7)) << 4);
            CP_ASYNC16(dst, gp);
        }
        CP_COMMIT();
    };

    int mbase = (wid >> 2) * 64;   // warp m offset (0/64)
    int nbase = (wid & 3) * 32;    // warp n offset (0/32/64/96)

    float acc[4][4][4];
#pragma unroll
    for (int mt = 0; mt < 4; mt++)
#pragma unroll
        for (int nt = 0; nt < 4; nt++)
#pragma unroll
            for (int e = 0; e < 4; e++) acc[mt][nt][e] = 0.f;

    issue(0, 0);
    if (nsteps > 1) issue(1, 1);

    for (int step = 0; step < nsteps; step++) {
        if (step + 1 < nsteps) { CP_WAIT(1); } else { CP_WAIT(0); }
        __syncthreads();

        uint32_t stb = sb + (step & 1) * 65536;
#pragma unroll
        for (int k16 = 0; k16 < 4; k16++) {
            uint32_t ahf[4][4], alf[4][4], bhf[2][4], blf[2][4];
            int arow = lane & 15;
            int ach = 2 * k16 + (lane >> 4);
#pragma unroll
            for (int mt = 0; mt < 4; mt++) {
                int row = mbase + mt * 16 + arow;
                uint32_t ad = stb + row * 128 + ((ach ^ (row & 7)) << 4);
                LDSM4(ahf[mt], ad);
                if (three_pass) LDSM4(alf[mt], ad + 16384);
            }
            int brow = (lane & 7) + ((lane >> 4) & 1) * 8;
            int bch = 2 * k16 + ((lane >> 3) & 1);
#pragma unroll
            for (int j = 0; j < 2; j++) {
                int row = nbase + j * 16 + brow;
                uint32_t bd = stb + 32768 + row * 128 + ((bch ^ (row & 7)) << 4);
                LDSM4(bhf[j], bd);
                if (three_pass) LDSM4(blf[j], bd + 16384);
            }
#pragma unroll
            for (int mt = 0; mt < 4; mt++)
#pragma unroll
                for (int nt = 0; nt < 4; nt++) {
                    int j = nt >> 1, p = (nt & 1) * 2;
                    MMA16816(acc[mt][nt], ahf[mt], bhf[j][p], bhf[j][p+1]);
                    if (three_pass) {
                        MMA16816(acc[mt][nt], ahf[mt], blf[j][p], blf[j][p+1]);
                        MMA16816(acc[mt][nt], alf[mt], bhf[j][p], bhf[j][p+1]);
                    }
                }
        }
        __syncthreads();
        if (step + 2 < nsteps) issue(step + 2, step & 1);
    }

    // epilogue
    float* Cc = C + zb * sC;
#pragma unroll
    for (int mt = 0; mt < 4; mt++) {
        int r0 = m0 + mbase + mt * 16 + (lane >> 2);
#pragma unroll
        for (int nt = 0; nt < 4; nt++) {
            int c = n0 + nbase + nt * 8 + 2 * (lane & 3);
            float b0 = 0.f, b1 = 0.f;
            if (bias) { b0 = bias[c]; b1 = bias[c + 1]; }
            float2 v0; v0.x = acc[mt][nt][0] + b0; v0.y = acc[mt][nt][1] + b1;
            *(float2*)&Cc[(long)r0 * N + c] = v0;
            float2 v1; v1.x = acc[mt][nt][2] + b0; v1.y = acc[mt][nt][3] + b1;
            *(float2*)&Cc[(long)(r0 + 8) * N + c] = v1;
        }
    }
}

// ---------------- weight transpose + split to bf16 ---------------------------
__global__ __launch_bounds__(256) void wt_split_kernel(
    const float* __restrict__ W, __nv_bfloat16* __restrict__ Th, __nv_bfloat16* __restrict__ Tl)
{
    __shared__ float t[32][33];
    int n0 = blockIdx.x * 32, k0 = blockIdx.y * 32;
    int tx = threadIdx.x, ty = threadIdx.y;
    for (int i = ty; i < 32; i += 8)
        t[i][tx] = W[(long)(k0 + i) * D_ + n0 + tx];
    __syncthreads();
    for (int i = ty; i < 32; i += 8) {
        float f = t[tx][i];
        __nv_bfloat16 h = __float2bfloat16(f);
        Th[(long)(n0 + i) * D_ + k0 + tx] = h;
        Tl[(long)(n0 + i) * D_ + k0 + tx] = __float2bfloat16(f - __bfloat162float(h));
    }
}

// ---------------- activation split (optional per-row gate scale) -------------
__global__ __launch_bounds__(256) void split_kernel(
    const float* __restrict__ src, __nv_bfloat16* __restrict__ h,
    __nv_bfloat16* __restrict__ l, int n4, const float* __restrict__ gate)
{
    int i = blockIdx.x * 256 + threadIdx.x;
    if (i >= n4) return;
    float4 f = ((const float4*)src)[i];
    if (gate) {
        float s = 1.0f + gate[(i * 4) >> 10] * (1.0f / 512.0f);
        f.x *= s; f.y *= s; f.z *= s; f.w *= s;
    }
    __nv_bfloat16 h0 = __float2bfloat16(f.x), h1 = __float2bfloat16(f.y);
    __nv_bfloat16 h2 = __float2bfloat16(f.z), h3 = __float2bfloat16(f.w);
    __nv_bfloat162 hv0; hv0.x = h0; hv0.y = h1;
    __nv_bfloat162 hv1; hv1.x = h2; hv1.y = h3;
    ((__nv_bfloat162*)h)[i*2+0] = hv0;
    ((__nv_bfloat162*)h)[i*2+1] = hv1;
    __nv_bfloat162 lv0, lv1;
    lv0.x = __float2bfloat16(f.x - __bfloat162float(h0));
    lv0.y = __float2bfloat16(f.y - __bfloat162float(h1));
    lv1.x = __float2bfloat16(f.z - __bfloat162float(h2));
    lv1.y = __float2bfloat16(f.w - __bfloat162float(h3));
    ((__nv_bfloat162*)l)[i*2+0] = lv0;
    ((__nv_bfloat162*)l)[i*2+1] = lv1;
}

// ------------- RMS-norm (q,k) + scatter q/k/v into [GH, SEQ, HD] -------------
__global__ __launch_bounds__(256) void rms_scatter_kernel(
    const float* __restrict__ qp, const float* __restrict__ kp,
    const float* __restrict__ vp,
    const float* __restrict__ qw, const float* __restrict__ kw,
    float* __restrict__ qs, float* __restrict__ ks, float* __restrict__ vs)
{
    int wid  = (blockIdx.x * 256 + threadIdx.x) >> 5;
    int lane = threadIdx.x & 31;
    int h  = wid & 15;
    int bn = wid >> 4;
    int b  = bn >> 9;
    long ibase = (long)bn * D_ + h * HD_;
    int g = b >> 2, inst = b & 3;
    int n = bn & 511;
    long obase = (((long)(g*16 + h)) * SEQ + inst*512 + n) * HD_;
    {
        float v0 = qp[ibase + lane], v1 = qp[ibase + lane + 32];
        float ss = v0*v0 + v1*v1;
#pragma unroll
        for (int off = 16; off; off >>= 1) ss += __shfl_xor_sync(0xffffffffu, ss, off);
        float sc = rsqrtf(ss * (1.0f/64.0f) + 1e-6f);
        qs[obase + lane]      = v0 * sc * qw[lane];
        qs[obase + lane + 32] = v1 * sc * qw[lane + 32];
    }
    {
        float v0 = kp[ibase + lane], v1 = kp[ibase + lane + 32];
        float ss = v0*v0 + v1*v1;
#pragma unroll
        for (int off = 16; off; off >>= 1) ss += __shfl_xor_sync(0xffffffffu, ss, off);
        float sc = rsqrtf(ss * (1.0f/64.0f) + 1e-6f);
        ks[obase + lane]      = v0 * sc * kw[lane];
        ks[obase + lane + 32] = v1 * sc * kw[lane + 32];
    }
    vs[obase + lane]      = vp[ibase + lane];
    vs[obase + lane + 32] = vp[ibase + lane + 32];
}

// ---------------- flash attention (fp32) --------------------------------------
#define FLASH_SMEM ((3*64*65 + 64*64) * 4)
__global__ __launch_bounds__(256) void flash_kernel(
    const float* __restrict__ Qg, const float* __restrict__ Kg,
    const float* __restrict__ Vg, float* __restrict__ Out)
{
    extern __shared__ float sm[];
    float* Qs = sm;
    float* Ks = Qs + 64*65;
    float* Ps = Ks + 64*65;
    float* Vs = Ps + 64*65;

    int tid = threadIdx.x;
    int qt  = blockIdx.x;
    int gh  = blockIdx.y;
    const float* Qbase = Qg + ((long)gh * SEQ + qt*64) * HD_;
    const float* Kb    = Kg + (long)gh * SEQ * HD_;
    const float* Vb    = Vg + (long)gh * SEQ * HD_;

#pragma unroll
    for (int u = tid; u < 1024; u += 256) {
        int row = u >> 4; int c4 = (u & 15) << 2;
        float4 v = *(const float4*)(Qbase + row*64 + c4);
        float* d = Qs + row*65 + c4;
        d[0] = v.x*SCALE; d[1] = v.y*SCALE; d[2] = v.z*SCALE; d[3] = v.w*SCALE;
    }

    int ty = tid >> 4, tx = tid & 15;
    int row0 = ty * 4;
    float acc[4][4];
    float mi[4], li[4];
#pragma unroll
    for (int i = 0; i < 4; i++) {
        mi[i] = -1e30f; li[i] = 0.f;
#pragma unroll
        for (int j = 0; j < 4; j++) acc[i][j] = 0.f;
    }

    for (int kt = 0; kt < 32; kt++) {
        __syncthreads();
#pragma unroll
        for (int u = tid; u < 1024; u += 256) {
            int row = u >> 4; int c4 = (u & 15) << 2;
            float4 kv = *(const float4*)(Kb + (long)(kt*64 + row)*64 + c4);
            float* d = Ks + row*65 + c4;
            d[0]=kv.x; d[1]=kv.y; d[2]=kv.z; d[3]=kv.w;
            float4 vv = *(const float4*)(Vb + (long)(kt*64 + row)*64 + c4);
            *(float4*)(Vs + row*64 + c4) = vv;
        }
        __syncthreads();

        float s[4][4];
#pragma unroll
        for (int i = 0; i < 4; i++)
#pragma unroll
            for (int j = 0; j < 4; j++) s[i][j] = 0.f;
#pragma unroll 4
        for (int d = 0; d < 64; d++) {
            float rq[4], rk[4];
#pragma unroll
            for (int i = 0; i < 4; i++) rq[i] = Qs[(row0+i)*65 + d];
#pragma unroll
            for (int j = 0; j < 4; j++) rk[j] = Ks[(tx + 16*j)*65 + d];
#pragma unroll
            for (int i = 0; i < 4; i++)
#pragma unroll
                for (int j = 0; j < 4; j++)
                    s[i][j] = fmaf(rq[i], rk[j], s[i][j]);
        }

#pragma unroll
        for (int i = 0; i < 4; i++) {
            float tm = fmaxf(fmaxf(s[i][0], s[i][1]), fmaxf(s[i][2], s[i][3]));
#pragma unroll
            for (int off = 8; off; off >>= 1)
                tm = fmaxf(tm, __shfl_xor_sync(0xffffffffu, tm, off, 16));
            float mnew = fmaxf(mi[i], tm);
            float corr = __expf(mi[i] - mnew);
            li[i] *= corr;
#pragma unroll
            for (int j = 0; j < 4; j++) acc[i][j] *= corr;
            mi[i] = mnew;
            float rs = 0.f;
#pragma unroll
            for (int j = 0; j < 4; j++) {
                float p = __expf(s[i][j] - mnew);
                Ps[(row0+i)*65 + tx + 16*j] = p;
                rs += p;
            }
#pragma unroll
            for (int off = 8; off; off >>= 1)
                rs += __shfl_xor_sync(0xffffffffu, rs, off, 16);
            li[i] += rs;
        }
        __syncthreads();

#pragma unroll 4
        for (int kk = 0; kk < 64; kk++) {
            float rp[4], rv[4];
#pragma unroll
            for (int i = 0; i < 4; i++) rp[i] = Ps[(row0+i)*65 + kk];
#pragma unroll
            for (int j = 0; j < 4; j++) rv[j] = Vs[kk*64 + tx + 16*j];
#pragma unroll
            for (int i = 0; i < 4; i++)
#pragma unroll
                for (int j = 0; j < 4; j++)
                    acc[i][j] = fmaf(rp[i], rv[j], acc[i][j]);
        }
    }

    int g = gh >> 4, h = gh & 15;
#pragma unroll
    for (int i = 0; i < 4; i++) {
        int r = qt*64 + row0 + i;
        int inst = r >> 9, n = r & 511;
        int b = g*4 + inst;
        float inv = 1.0f / li[i];
        float* orow = Out + ((long)(b*512 + n)) * D_ + h * HD_;
#pragma unroll
        for (int j = 0; j < 4; j++)
            orow[tx + 16*j] = acc[i][j] * inv;
    }
}

// ---------------- instance feature: feat = mask @ embed[:4] ------------------
__global__ __launch_bounds__(256) void feat_kernel(
    const float* __restrict__ mask, const float* __restrict__ embed,
    float* __restrict__ feat)
{
    int row = blockIdx.x;
    float m0 = mask[row*4+0], m1 = mask[row*4+1];
    float m2 = mask[row*4+2], m3 = mask[row*4+3];
    for (int c = threadIdx.x; c < D_; c += 256)
        feat[(long)row*D_ + c] = m0*embed[c] + m1*embed[D_ + c]
                               + m2*embed[2*D_ + c] + m3*embed[3*D_ + c];
}

// ---------------- sigmoid row-reduction of gate scores -----------------------
__global__ void sigred_kernel(const float* __restrict__ S, float* __restrict__ gacc)
{
    int row = blockIdx.x * 8 + threadIdx.y;   // grid 512, block 32x8
    const float* p = S + (long)row * 512;
    float s = 0.f;
    for (int i = threadIdx.x; i < 512; i += 32) {
        float x = p[i] * S2;
        s += 1.0f / (1.0f + __expf(-x));
    }
#pragma unroll
    for (int o = 16; o; o >>= 1) s += __shfl_xor_sync(0xffffffffu, s, o);
    if (threadIdx.x == 0) gacc[row] = s;
}

// ------------------------------- launch --------------------------------------
extern "C" void kernel_launch(void* const* d_in, const int* in_sizes, int n_in,
                              void* d_out, int out_size)
{
    const float* x     = (const float*)d_in[0];
    const float* mask  = (const float*)d_in[1];
    const float* Wq    = (const float*)d_in[2];
    const float* bq    = (const float*)d_in[3];
    const float* Wk    = (const float*)d_in[4];
    const float* bk    = (const float*)d_in[5];
    const float* Wv    = (const float*)d_in[6];
    const float* bv    = (const float*)d_in[7];
    const float* Wo    = (const float*)d_in[8];
    const float* bo    = (const float*)d_in[9];
    const float* Wiq   = (const float*)d_in[10];
    const float* biq   = (const float*)d_in[11];
    const float* Wik   = (const float*)d_in[12];
    const float* bik   = (const float*)d_in[13];
    const float* embed = (const float*)d_in[14];
    const float* qw    = (const float*)d_in[15];
    const float* kw    = (const float*)d_in[16];
    float* out = (float*)d_out;

    float *qp,*kp,*vp,*qs,*ks,*vs,*attn,*feat,*iq,*ik,*gacc,*scores;
    cudaGetSymbolAddress((void**)&qp, g_qp);     cudaGetSymbolAddress((void**)&kp, g_kp);
    cudaGetSymbolAddress((void**)&vp, g_vp);     cudaGetSymbolAddress((void**)&qs, g_qs);
    cudaGetSymbolAddress((void**)&ks, g_ks);     cudaGetSymbolAddress((void**)&vs, g_vs);
    cudaGetSymbolAddress((void**)&attn, g_attn); cudaGetSymbolAddress((void**)&feat, g_feat);
    cudaGetSymbolAddress((void**)&iq, g_iq);     cudaGetSymbolAddress((void**)&ik, g_ik);
    cudaGetSymbolAddress((void**)&gacc, g_gacc); cudaGetSymbolAddress((void**)&scores, g_scores);

    __nv_bfloat16 *wqh,*wql,*wkh,*wkl,*wvh,*wvl,*wiqh,*wiql,*wikh,*wikl,*woh,*wol;
    __nv_bfloat16 *xh,*xl,*ah,*al,*fh,*fl,*iqh,*iql,*ikh,*ikl,*gth,*gtl;
    cudaGetSymbolAddress((void**)&wqh, g_wqh);   cudaGetSymbolAddress((void**)&wql, g_wql);
    cudaGetSymbolAddress((void**)&wkh, g_wkh);   cudaGetSymbolAddress((void**)&wkl, g_wkl);
    cudaGetSymbolAddress((void**)&wvh, g_wvh);   cudaGetSymbolAddress((void**)&wvl, g_wvl);
    cudaGetSymbolAddress((void**)&wiqh, g_wiqh); cudaGetSymbolAddress((void**)&wiql, g_wiql);
    cudaGetSymbolAddress((void**)&wikh, g_wikh); cudaGetSymbolAddress((void**)&wikl, g_wikl);
    cudaGetSymbolAddress((void**)&woh, g_woh);   cudaGetSymbolAddress((void**)&wol, g_wol);
    cudaGetSymbolAddress((void**)&xh, g_xh);     cudaGetSymbolAddress((void**)&xl, g_xl);
    cudaGetSymbolAddress((void**)&ah, g_ah);     cudaGetSymbolAddress((void**)&al, g_al);
    cudaGetSymbolAddress((void**)&fh, g_fh);     cudaGetSymbolAddress((void**)&fl, g_fl);
    cudaGetSymbolAddress((void**)&iqh, g_iqh);   cudaGetSymbolAddress((void**)&iql, g_iql);
    cudaGetSymbolAddress((void**)&ikh, g_ikh);   cudaGetSymbolAddress((void**)&ikl, g_ikl);
    cudaGetSymbolAddress((void**)&gth, g_gth);   cudaGetSymbolAddress((void**)&gtl, g_gtl);

    cudaFuncSetAttribute((const void*)flash_kernel,
                         cudaFuncAttributeMaxDynamicSharedMemorySize, FLASH_SMEM);
    cudaFuncSetAttribute((const void*)mma_gemm_kernel,
                         cudaFuncAttributeMaxDynamicSharedMemorySize, TC_SMEM);

    dim3 wtg(32, 32);
    dim3 wtb(32, 8);
    const int N4 = MROWS * D_ / 4;
    const int SPLIT_BLOCKS = (N4 + 255) / 256;
    dim3 big_grid(D_/128, MROWS/128, 1);   // (8, 32)

    // weight prep (transpose + split)
    wt_split_kernel<<<wtg, wtb>>>(Wq,  wqh,  wql);
    wt_split_kernel<<<wtg, wtb>>>(Wk,  wkh,  wkl);
    wt_split_kernel<<<wtg, wtb>>>(Wv,  wvh,  wvl);
    wt_split_kernel<<<wtg, wtb>>>(Wiq, wiqh, wiql);
    wt_split_kernel<<<wtg, wtb>>>(Wik, wikh, wikl);
    wt_split_kernel<<<wtg, wtb>>>(Wo,  woh,  wol);

    // x split + QKV projections (3-pass split bf16)
    split_kernel<<<SPLIT_BLOCKS, 256>>>(x, xh, xl, N4, nullptr);
    mma_gemm_kernel<<<big_grid, 256, TC_SMEM>>>(xh, xl, wqh, wql, bq, qp, MROWS, D_, D_, 0, 0, 0, 1);
    mma_gemm_kernel<<<big_grid, 256, TC_SMEM>>>(xh, xl, wkh, wkl, bk, kp, MROWS, D_, D_, 0, 0, 0, 1);
    mma_gemm_kernel<<<big_grid, 256, TC_SMEM>>>(xh, xl, wvh, wvl, bv, vp, MROWS, D_, D_, 0, 0, 0, 1);

    // per-head RMS norm + scatter; attention
    rms_scatter_kernel<<<(MROWS*H_)/8, 256>>>(qp, kp, vp, qw, kw, qs, ks, vs);
    flash_kernel<<<dim3(SEQ/64, GH), 256, FLASH_SMEM>>>(qs, ks, vs, attn);

    // instance features; splits
    feat_kernel<<<MROWS, 256>>>(mask, embed, feat);
    split_kernel<<<SPLIT_BLOCKS, 256>>>(attn, ah, al, N4, nullptr);
    split_kernel<<<SPLIT_BLOCKS, 256>>>(feat, fh, fl, N4, nullptr);

    // iq / ik projections (1-pass: feeds only the sigmoid-mean gate)
    mma_gemm_kernel<<<big_grid, 256, TC_SMEM>>>(ah, al, wiqh, wiql, biq, iq, MROWS, D_, D_, 0, 0, 0, 0);
    mma_gemm_kernel<<<big_grid, 256, TC_SMEM>>>(fh, fl, wikh, wikl, bik, ik, MROWS, D_, D_, 0, 0, 0, 0);

    // gate scores: per-batch iq @ ik^T (1-pass bf16)
    split_kernel<<<SPLIT_BLOCKS, 256>>>(iq, iqh, iql, N4, nullptr);
    split_kernel<<<SPLIT_BLOCKS, 256>>>(ik, ikh, ikl, N4, nullptr);
    mma_gemm_kernel<<<dim3(4, 4, 8), 256, TC_SMEM>>>(iqh, iql, ikh, ikl, nullptr, scores,
                                                     512, 512, D_,
                                                     (long)512*D_, (long)512*D_, (long)512*512, 0);
    sigred_kernel<<<512, dim3(32, 8)>>>(scores, gacc);

    // gated output projection (3-pass)
    split_kernel<<<SPLIT_BLOCKS, 256>>>(attn, gth, gtl, N4, gacc);
    mma_gemm_kernel<<<big_grid, 256, TC_SMEM>>>(gth, gtl, woh, wol, bo, out, MROWS, D_, D_, 0, 0, 0, 1);
}

// round 4
// speedup vs baseline: 3.0114x; 1.8899x over previous
#include <cuda_runtime.h>
#include <cuda_bf16.h>
#include <math.h>
#include <stdint.h>

// Problem constants
#define B_    8
#define N_    512
#define D_    1024
#define H_    16
#define HD_   64
#define NI_   4
#define G_    2
#define MROWS (B_*N_)      // 4096
#define SEQ   (NI_*N_)     // 2048
#define GH    (G_*H_)      // 32
#define SCALE 0.125f
#define S2    0.0078125f   // SCALE / H

// ---------------- scratch (device globals) -----------------------------------
static __device__ float g_qp[MROWS*D_];
static __device__ float g_kp[MROWS*D_];
static __device__ float g_vp[MROWS*D_];
static __device__ float g_attn[MROWS*D_];
static __device__ float g_feat[MROWS*D_];
static __device__ float g_iq[MROWS*D_];
static __device__ float g_ik[MROWS*D_];
static __device__ float g_gacc[MROWS];
static __device__ float g_scores[B_*N_*N_];   // 8 x 512 x 512

// attention operand buffers: bf16 hi/lo, grouped layout [GH, SEQ, HD]
#define AELEMS (GH*SEQ*HD_)
static __device__ __align__(256) __nv_bfloat16 g_qhg[AELEMS], g_qlg[AELEMS];
static __device__ __align__(256) __nv_bfloat16 g_khg[AELEMS], g_klg[AELEMS];
static __device__ __align__(256) __nv_bfloat16 g_vhg[AELEMS], g_vlg[AELEMS];

// split-bf16 weight (transposed [N,K]) and activation buffers
static __device__ __align__(256) __nv_bfloat16 g_wqh[D_*D_], g_wql[D_*D_];
static __device__ __align__(256) __nv_bfloat16 g_wkh[D_*D_], g_wkl[D_*D_];
static __device__ __align__(256) __nv_bfloat16 g_wvh[D_*D_], g_wvl[D_*D_];
static __device__ __align__(256) __nv_bfloat16 g_wiqh[D_*D_], g_wiql[D_*D_];
static __device__ __align__(256) __nv_bfloat16 g_wikh[D_*D_], g_wikl[D_*D_];
static __device__ __align__(256) __nv_bfloat16 g_woh[D_*D_], g_wol[D_*D_];
static __device__ __align__(256) __nv_bfloat16 g_xh[MROWS*D_],  g_xl[MROWS*D_];
static __device__ __align__(256) __nv_bfloat16 g_ah[MROWS*D_],  g_al[MROWS*D_];
static __device__ __align__(256) __nv_bfloat16 g_fh[MROWS*D_],  g_fl[MROWS*D_];
static __device__ __align__(256) __nv_bfloat16 g_iqh[MROWS*D_], g_iql[MROWS*D_];
static __device__ __align__(256) __nv_bfloat16 g_ikh[MROWS*D_], g_ikl[MROWS*D_];
static __device__ __align__(256) __nv_bfloat16 g_gth[MROWS*D_], g_gtl[MROWS*D_];

// ---------------- PTX helpers --------------------------------------------------
__device__ __forceinline__ uint32_t smem_u32(const void* p) {
    uint32_t a;
    asm("{ .reg .u64 t; cvta.to.shared.u64 t, %1; cvt.u32.u64 %0, t; }"
        : "=r"(a) : "l"(p));
    return a;
}

#define LDSM4(r, addr) \
    asm volatile("ldmatrix.sync.aligned.m8n8.x4.shared.b16 {%0,%1,%2,%3}, [%4];" \
        : "=r"((r)[0]), "=r"((r)[1]), "=r"((r)[2]), "=r"((r)[3]) : "r"(addr))

#define LDSM4T(r, addr) \
    asm volatile("ldmatrix.sync.aligned.m8n8.x4.trans.shared.b16 {%0,%1,%2,%3}, [%4];" \
        : "=r"((r)[0]), "=r"((r)[1]), "=r"((r)[2]), "=r"((r)[3]) : "r"(addr))

#define MMA16816(d, a, bv0, bv1) \
    asm volatile("mma.sync.aligned.m16n8k16.row.col.f32.bf16.bf16.f32 " \
        "{%0,%1,%2,%3}, {%4,%5,%6,%7}, {%8,%9}, {%0,%1,%2,%3};" \
        : "+f"((d)[0]), "+f"((d)[1]), "+f"((d)[2]), "+f"((d)[3]) \
        : "r"((a)[0]), "r"((a)[1]), "r"((a)[2]), "r"((a)[3]), "r"(bv0), "r"(bv1))

#define CP_ASYNC16(dst, src) \
    asm volatile("cp.async.cg.shared.global [%0], [%1], 16;" \
        :: "r"(dst), "l"(__cvta_generic_to_global(src)) : "memory")
#define CP_COMMIT() asm volatile("cp.async.commit_group;" ::: "memory")
#define CP_WAIT(n)  asm volatile("cp.async.wait_group %0;" :: "n"(n) : "memory")

__device__ __forceinline__ uint32_t packbf(float a, float b) {
    // result: low half = bf16(a), high half = bf16(b)
    uint32_t d;
    asm("cvt.rn.bf16x2.f32 %0, %1, %2;" : "=r"(d) : "f"(b), "f"(a));
    return d;
}
__device__ __forceinline__ float bflo(uint32_t v) { return __uint_as_float(v << 16); }
__device__ __forceinline__ float bfhi(uint32_t v) { return __uint_as_float(v & 0xffff0000u); }

// ---------------- HMMA split-bf16 GEMM (unchanged, proven) --------------------
#define TC_SMEM (2*4*16384)   // 131072
__global__ __launch_bounds__(256, 1)
void mma_gemm_kernel(const __nv_bfloat16* __restrict__ Ahp, const __nv_bfloat16* __restrict__ Alp,
                     const __nv_bfloat16* __restrict__ Bhp, const __nv_bfloat16* __restrict__ Blp,
                     const float* __restrict__ bias, float* __restrict__ C,
                     int M, int N, int K, long sA, long sB, long sC, int three_pass)
{
    extern __shared__ char smem[];
    uint32_t sb = smem_u32(smem);
    int tid = threadIdx.x, wid = tid >> 5, lane = tid & 31;
    int m0 = blockIdx.y * 128, n0 = blockIdx.x * 128;
    long zb = blockIdx.z;
    const __nv_bfloat16* Ah = Ahp + zb * sA;
    const __nv_bfloat16* Al = Alp + zb * sA;
    const __nv_bfloat16* Bh = Bhp + zb * sB;
    const __nv_bfloat16* Bl = Blp + zb * sB;

    const int nsteps = K / 64;

    auto issue = [&](int step, int stage) {
        uint32_t stb = sb + stage * 65536;
        int k0 = step * 64;
#pragma unroll
        for (int i = 0; i < 16; i++) {
            int c = i * 256 + tid;
            int tile = c >> 10;
            int w = c & 1023;
            int row = w >> 3, ch = w & 7;
            const __nv_bfloat16* src;
            int gr;
            if      (tile == 0) { src = Ah; gr = m0 + row; }
            else if (tile == 1) { src = Al; gr = m0 + row; }
            else if (tile == 2) { src = Bh; gr = n0 + row; }
            else                { src = Bl; gr = n0 + row; }
            const __nv_bfloat16* gp = src + (long)gr * K + k0 + ch * 8;
            uint32_t dst = stb + tile * 16384 + row * 128 + ((ch ^ (row & 7)) << 4);
            CP_ASYNC16(dst, gp);
        }
        CP_COMMIT();
    };

    int mbase = (wid >> 2) * 64;
    int nbase = (wid & 3) * 32;

    float acc[4][4][4];
#pragma unroll
    for (int mt = 0; mt < 4; mt++)
#pragma unroll
        for (int nt = 0; nt < 4; nt++)
#pragma unroll
            for (int e = 0; e < 4; e++) acc[mt][nt][e] = 0.f;

    issue(0, 0);
    if (nsteps > 1) issue(1, 1);

    for (int step = 0; step < nsteps; step++) {
        if (step + 1 < nsteps) { CP_WAIT(1); } else { CP_WAIT(0); }
        __syncthreads();

        uint32_t stb = sb + (step & 1) * 65536;
#pragma unroll
        for (int k16 = 0; k16 < 4; k16++) {
            uint32_t ahf[4][4], alf[4][4], bhf[2][4], blf[2][4];
            int arow = lane & 15;
            int ach = 2 * k16 + (lane >> 4);
#pragma unroll
            for (int mt = 0; mt < 4; mt++) {
                int row = mbase + mt * 16 + arow;
                uint32_t ad = stb + row * 128 + ((ach ^ (row & 7)) << 4);
                LDSM4(ahf[mt], ad);
                if (three_pass) LDSM4(alf[mt], ad + 16384);
            }
            int brow = (lane & 7) + ((lane >> 4) & 1) * 8;
            int bch = 2 * k16 + ((lane >> 3) & 1);
#pragma unroll
            for (int j = 0; j < 2; j++) {
                int row = nbase + j * 16 + brow;
                uint32_t bd = stb + 32768 + row * 128 + ((bch ^ (row & 7)) << 4);
                LDSM4(bhf[j], bd);
                if (three_pass) LDSM4(blf[j], bd + 16384);
            }
#pragma unroll
            for (int mt = 0; mt < 4; mt++)
#pragma unroll
                for (int nt = 0; nt < 4; nt++) {
                    int j = nt >> 1, p = (nt & 1) * 2;
                    MMA16816(acc[mt][nt], ahf[mt], bhf[j][p], bhf[j][p+1]);
                    if (three_pass) {
                        MMA16816(acc[mt][nt], ahf[mt], blf[j][p], blf[j][p+1]);
                        MMA16816(acc[mt][nt], alf[mt], bhf[j][p], bhf[j][p+1]);
                    }
                }
        }
        __syncthreads();
        if (step + 2 < nsteps) issue(step + 2, step & 1);
    }

    float* Cc = C + zb * sC;
#pragma unroll
    for (int mt = 0; mt < 4; mt++) {
        int r0 = m0 + mbase + mt * 16 + (lane >> 2);
#pragma unroll
        for (int nt = 0; nt < 4; nt++) {
            int c = n0 + nbase + nt * 8 + 2 * (lane & 3);
            float b0 = 0.f, b1 = 0.f;
            if (bias) { b0 = bias[c]; b1 = bias[c + 1]; }
            float2 v0; v0.x = acc[mt][nt][0] + b0; v0.y = acc[mt][nt][1] + b1;
            *(float2*)&Cc[(long)r0 * N + c] = v0;
            float2 v1; v1.x = acc[mt][nt][2] + b0; v1.y = acc[mt][nt][3] + b1;
            *(float2*)&Cc[(long)(r0 + 8) * N + c] = v1;
        }
    }
}

// ---------------- weight transpose + split to bf16 ---------------------------
__global__ __launch_bounds__(256) void wt_split_kernel(
    const float* __restrict__ W, __nv_bfloat16* __restrict__ Th, __nv_bfloat16* __restrict__ Tl)
{
    __shared__ float t[32][33];
    int n0 = blockIdx.x * 32, k0 = blockIdx.y * 32;
    int tx = threadIdx.x, ty = threadIdx.y;
    for (int i = ty; i < 32; i += 8)
        t[i][tx] = W[(long)(k0 + i) * D_ + n0 + tx];
    __syncthreads();
    for (int i = ty; i < 32; i += 8) {
        float f = t[tx][i];
        __nv_bfloat16 h = __float2bfloat16(f);
        Th[(long)(n0 + i) * D_ + k0 + tx] = h;
        Tl[(long)(n0 + i) * D_ + k0 + tx] = __float2bfloat16(f - __bfloat162float(h));
    }
}

// ---------------- activation split (optional per-row gate scale) -------------
__global__ __launch_bounds__(256) void split_kernel(
    const float* __restrict__ src, __nv_bfloat16* __restrict__ h,
    __nv_bfloat16* __restrict__ l, int n4, const float* __restrict__ gate)
{
    int i = blockIdx.x * 256 + threadIdx.x;
    if (i >= n4) return;
    float4 f = ((const float4*)src)[i];
    if (gate) {
        float s = 1.0f + gate[(i * 4) >> 10] * (1.0f / 512.0f);
        f.x *= s; f.y *= s; f.z *= s; f.w *= s;
    }
    __nv_bfloat16 h0 = __float2bfloat16(f.x), h1 = __float2bfloat16(f.y);
    __nv_bfloat16 h2 = __float2bfloat16(f.z), h3 = __float2bfloat16(f.w);
    __nv_bfloat162 hv0; hv0.x = h0; hv0.y = h1;
    __nv_bfloat162 hv1; hv1.x = h2; hv1.y = h3;
    ((__nv_bfloat162*)h)[i*2+0] = hv0;
    ((__nv_bfloat162*)h)[i*2+1] = hv1;
    __nv_bfloat162 lv0, lv1;
    lv0.x = __float2bfloat16(f.x - __bfloat162float(h0));
    lv0.y = __float2bfloat16(f.y - __bfloat162float(h1));
    lv1.x = __float2bfloat16(f.z - __bfloat162float(h2));
    lv1.y = __float2bfloat16(f.w - __bfloat162float(h3));
    ((__nv_bfloat162*)l)[i*2+0] = lv0;
    ((__nv_bfloat162*)l)[i*2+1] = lv1;
}

// ------- RMS-norm (q,k) + split to bf16 hi/lo, scatter into [GH, SEQ, HD] ----
__global__ __launch_bounds__(256) void rms_scatter_kernel(
    const float* __restrict__ qp, const float* __restrict__ kp,
    const float* __restrict__ vp,
    const float* __restrict__ qw, const float* __restrict__ kw,
    __nv_bfloat16* __restrict__ qh, __nv_bfloat16* __restrict__ ql,
    __nv_bfloat16* __restrict__ kh, __nv_bfloat16* __restrict__ kl,
    __nv_bfloat16* __restrict__ vh, __nv_bfloat16* __restrict__ vl)
{
    int wid  = (blockIdx.x * 256 + threadIdx.x) >> 5;
    int lane = threadIdx.x & 31;
    int h  = wid & 15;
    int bn = wid >> 4;
    int b  = bn >> 9;
    long ibase = (long)bn * D_ + h * HD_;
    int g = b >> 2, inst = b & 3;
    int n = bn & 511;
    long obase = (((long)(g*16 + h)) * SEQ + inst*512 + n) * HD_;

    auto emit = [&](float v, __nv_bfloat16* ph, __nv_bfloat16* pl, long off) {
        __nv_bfloat16 hb = __float2bfloat16(v);
        ph[off] = hb;
        pl[off] = __float2bfloat16(v - __bfloat162float(hb));
    };
    {
        float v0 = qp[ibase + lane], v1 = qp[ibase + lane + 32];
        float ss = v0*v0 + v1*v1;
#pragma unroll
        for (int off = 16; off; off >>= 1) ss += __shfl_xor_sync(0xffffffffu, ss, off);
        float sc = rsqrtf(ss * (1.0f/64.0f) + 1e-6f) * SCALE;
        emit(v0 * sc * qw[lane],      qh, ql, obase + lane);
        emit(v1 * sc * qw[lane + 32], qh, ql, obase + lane + 32);
    }
    {
        float v0 = kp[ibase + lane], v1 = kp[ibase + lane + 32];
        float ss = v0*v0 + v1*v1;
#pragma unroll
        for (int off = 16; off; off >>= 1) ss += __shfl_xor_sync(0xffffffffu, ss, off);
        float sc = rsqrtf(ss * (1.0f/64.0f) + 1e-6f);
        emit(v0 * sc * kw[lane],      kh, kl, obase + lane);
        emit(v1 * sc * kw[lane + 32], kh, kl, obase + lane + 32);
    }
    emit(vp[ibase + lane],      vh, vl, obase + lane);
    emit(vp[ibase + lane + 32], vh, vl, obase + lane + 32);
}

// ---------------- flash attention via mma.sync (split-bf16 3-pass) -----------
// grid (16 q-tiles of 128, 32 gh), 256 threads (8 warps x 16 q rows).
// SMEM: 2 stages x {Kh,Kl,Vh,Vl}[128x64 bf16] (64KB each) + {Qh,Ql} (32KB)
#define FL_SMEM (2*65536 + 32768)
__global__ __launch_bounds__(256, 1)
void flash_mma_kernel(const __nv_bfloat16* __restrict__ Qh_, const __nv_bfloat16* __restrict__ Ql_,
                      const __nv_bfloat16* __restrict__ Kh_, const __nv_bfloat16* __restrict__ Kl_,
                      const __nv_bfloat16* __restrict__ Vh_, const __nv_bfloat16* __restrict__ Vl_,
                      float* __restrict__ Out)
{
    extern __shared__ char smem[];
    uint32_t sb = smem_u32(smem);
    int tid = threadIdx.x, wid = tid >> 5, lane = tid & 31;
    int qt = blockIdx.x, gh = blockIdx.y;
    long ghoff = (long)gh * SEQ * HD_;
    const __nv_bfloat16* Qh = Qh_ + ghoff + (long)qt * 128 * HD_;
    const __nv_bfloat16* Ql = Ql_ + ghoff + (long)qt * 128 * HD_;
    const __nv_bfloat16* Kh = Kh_ + ghoff;
    const __nv_bfloat16* Kl = Kl_ + ghoff;
    const __nv_bfloat16* Vh = Vh_ + ghoff;
    const __nv_bfloat16* Vl = Vl_ + ghoff;

    const uint32_t QOFF = 131072;

    // issue Q (one group)
    {
#pragma unroll
        for (int i = 0; i < 8; i++) {
            int c = i * 256 + tid;
            int arr = c >> 10, w = c & 1023, row = w >> 3, ch = w & 7;
            const __nv_bfloat16* src = (arr ? Ql : Qh) + (long)row * 64 + ch * 8;
            uint32_t dst = sb + QOFF + arr * 16384 + row * 128 + ((ch ^ (row & 7)) << 4);
            CP_ASYNC16(dst, src);
        }
        CP_COMMIT();
    }

    auto issueKV = [&](int it, int stage) {
        uint32_t stb = sb + stage * 65536;
#pragma unroll
        for (int i = 0; i < 16; i++) {
            int c = i * 256 + tid;
            int arr = c >> 10, w = c & 1023, row = w >> 3, ch = w & 7;
            const __nv_bfloat16* src;
            if      (arr == 0) src = Kh;
            else if (arr == 1) src = Kl;
            else if (arr == 2) src = Vh;
            else               src = Vl;
            src += (long)(it * 128 + row) * 64 + ch * 8;
            uint32_t dst = stb + arr * 16384 + row * 128 + ((ch ^ (row & 7)) << 4);
            CP_ASYNC16(dst, src);
        }
        CP_COMMIT();
    };

    issueKV(0, 0);
    issueKV(1, 1);
    CP_WAIT(1);           // Q + stage0 done, stage1 in flight
    __syncthreads();

    // Q fragments in registers for the whole kernel
    uint32_t qhf[4][4], qlf[4][4];
    {
        int arow = lane & 15;
#pragma unroll
        for (int kt = 0; kt < 4; kt++) {
            int row = wid * 16 + arow;
            int ach = 2 * kt + (lane >> 4);
            uint32_t ad = sb + QOFF + row * 128 + ((ach ^ (row & 7)) << 4);
            LDSM4(qhf[kt], ad);
            LDSM4(qlf[kt], ad + 16384);
        }
    }

    float o[8][4];
#pragma unroll
    for (int nt = 0; nt < 8; nt++)
#pragma unroll
        for (int e = 0; e < 4; e++) o[nt][e] = 0.f;
    float m0 = -1e30f, m1 = -1e30f, lp0 = 0.f, lp1 = 0.f;

    for (int it = 0; it < 16; it++) {
        if (it > 0) {
            if (it < 15) { CP_WAIT(1); } else { CP_WAIT(0); }
            __syncthreads();
        }
        uint32_t stb = sb + (it & 1) * 65536;

        // ---- S = Qs @ Ks^T (3-pass), 16 n-tiles of 8 kv cols ----
        float s[16][4];
#pragma unroll
        for (int t = 0; t < 16; t++)
#pragma unroll
            for (int e = 0; e < 4; e++) s[t][e] = 0.f;

        int brow = (lane & 7) + ((lane >> 4) & 1) * 8;
#pragma unroll
        for (int kt = 0; kt < 4; kt++) {
            int bch = 2 * kt + ((lane >> 3) & 1);
#pragma unroll
            for (int jj = 0; jj < 8; jj++) {
                int row = jj * 16 + brow;
                uint32_t bd = stb + row * 128 + ((bch ^ (row & 7)) << 4);
                uint32_t khf[4], klf[4];
                LDSM4(khf, bd);
                LDSM4(klf, bd + 16384);
                MMA16816(s[2*jj],   qhf[kt], khf[0], khf[1]);
                MMA16816(s[2*jj],   qhf[kt], klf[0], klf[1]);
                MMA16816(s[2*jj],   qlf[kt], khf[0], khf[1]);
                MMA16816(s[2*jj+1], qhf[kt], khf[2], khf[3]);
                MMA16816(s[2*jj+1], qhf[kt], klf[2], klf[3]);
                MMA16816(s[2*jj+1], qlf[kt], khf[2], khf[3]);
            }
        }

        // ---- online softmax (rows: lane>>2 and +8) ----
        float t0 = -1e30f, t1 = -1e30f;
#pragma unroll
        for (int t = 0; t < 16; t++) {
            t0 = fmaxf(t0, fmaxf(s[t][0], s[t][1]));
            t1 = fmaxf(t1, fmaxf(s[t][2], s[t][3]));
        }
        t0 = fmaxf(t0, __shfl_xor_sync(0xffffffffu, t0, 1, 4));
        t0 = fmaxf(t0, __shfl_xor_sync(0xffffffffu, t0, 2, 4));
        t1 = fmaxf(t1, __shfl_xor_sync(0xffffffffu, t1, 1, 4));
        t1 = fmaxf(t1, __shfl_xor_sync(0xffffffffu, t1, 2, 4));
        float mn0 = fmaxf(m0, t0), mn1 = fmaxf(m1, t1);
        float c0 = __expf(m0 - mn0), c1 = __expf(m1 - mn1);
        m0 = mn0; m1 = mn1;
        lp0 *= c0; lp1 *= c1;
#pragma unroll
        for (int nt = 0; nt < 8; nt++) {
            o[nt][0] *= c0; o[nt][1] *= c0;
            o[nt][2] *= c1; o[nt][3] *= c1;
        }
#pragma unroll
        for (int t = 0; t < 16; t++) {
            s[t][0] = __expf(s[t][0] - m0);
            s[t][1] = __expf(s[t][1] - m0);
            s[t][2] = __expf(s[t][2] - m1);
            s[t][3] = __expf(s[t][3] - m1);
            lp0 += s[t][0] + s[t][1];
            lp1 += s[t][2] + s[t][3];
        }

        // ---- O += P @ V (3-pass), k = kv (8 k16 steps), n = hd (8 n-tiles) ----
        int vrow = lane & 15;
#pragma unroll
        for (int kt = 0; kt < 8; kt++) {
            // A fragments from P (S accum repack)
            uint32_t pha[4], pla[4];
#pragma unroll
            for (int q = 0; q < 2; q++) {           // q=0: regs 0,1 (tile 2kt); q=1: regs 2,3 (tile 2kt+1)
                float a0 = s[2*kt + q][0], a1 = s[2*kt + q][1];
                float a2 = s[2*kt + q][2], a3 = s[2*kt + q][3];
                uint32_t h0 = packbf(a0, a1);
                uint32_t h1 = packbf(a2, a3);
                pha[2*q]   = h0;
                pha[2*q+1] = h1;
                pla[2*q]   = packbf(a0 - bflo(h0), a1 - bfhi(h0));
                pla[2*q+1] = packbf(a2 - bflo(h1), a3 - bfhi(h1));
            }
            int row = kt * 16 + vrow;
#pragma unroll
            for (int nt4 = 0; nt4 < 4; nt4++) {
                int ch = 2 * nt4 + (lane >> 4);
                uint32_t vd = stb + 32768 + row * 128 + ((ch ^ (row & 7)) << 4);
                uint32_t vhf[4], vlf[4];
                LDSM4T(vhf, vd);
                LDSM4T(vlf, vd + 16384);
                MMA16816(o[2*nt4],   pha, vhf[0], vhf[1]);
                MMA16816(o[2*nt4],   pha, vlf[0], vlf[1]);
                MMA16816(o[2*nt4],   pla, vhf[0], vhf[1]);
                MMA16816(o[2*nt4+1], pha, vhf[2], vhf[3]);
                MMA16816(o[2*nt4+1], pha, vlf[2], vlf[3]);
                MMA16816(o[2*nt4+1], pla, vhf[2], vhf[3]);
            }
        }

        __syncthreads();
        if (it + 2 < 16) issueKV(it + 2, it & 1);
    }

    // ---- epilogue: row-sum reduce, normalize, scatter to [B*N, D] ----
    lp0 += __shfl_xor_sync(0xffffffffu, lp0, 1, 4);
    lp0 += __shfl_xor_sync(0xffffffffu, lp0, 2, 4);
    lp1 += __shfl_xor_sync(0xffffffffu, lp1, 1, 4);
    lp1 += __shfl_xor_sync(0xffffffffu, lp1, 2, 4);
    float inv0 = 1.0f / lp0, inv1 = 1.0f / lp1;

    int g = gh >> 4, h = gh & 15;
#pragma unroll
    for (int e = 0; e < 2; e++) {
        int r = qt * 128 + wid * 16 + (lane >> 2) + 8 * e;
        int inst = r >> 9, n = r & 511;
        int b = g * 4 + inst;
        float inv = e ? inv1 : inv0;
        float* orow = Out + ((long)(b * 512 + n)) * D_ + h * HD_;
#pragma unroll
        for (int nt = 0; nt < 8; nt++) {
            float2 v;
            v.x = o[nt][2*e]   * inv;
            v.y = o[nt][2*e+1] * inv;
            *(float2*)&orow[nt * 8 + 2 * (lane & 3)] = v;
        }
    }
}

// ---------------- instance feature: feat = mask @ embed[:4] ------------------
__global__ __launch_bounds__(256) void feat_kernel(
    const float* __restrict__ mask, const float* __restrict__ embed,
    float* __restrict__ feat)
{
    int row = blockIdx.x;
    float m0 = mask[row*4+0], m1 = mask[row*4+1];
    float m2 = mask[row*4+2], m3 = mask[row*4+3];
    for (int c = threadIdx.x; c < D_; c += 256)
        feat[(long)row*D_ + c] = m0*embed[c] + m1*embed[D_ + c]
                               + m2*embed[2*D_ + c] + m3*embed[3*D_ + c];
}

// ---------------- sigmoid row-reduction of gate scores -----------------------
__global__ void sigred_kernel(const float* __restrict__ S, float* __restrict__ gacc)
{
    int row = blockIdx.x * 8 + threadIdx.y;
    const float* p = S + (long)row * 512;
    float s = 0.f;
    for (int i = threadIdx.x; i < 512; i += 32) {
        float x = p[i] * S2;
        s += 1.0f / (1.0f + __expf(-x));
    }
#pragma unroll
    for (int o = 16; o; o >>= 1) s += __shfl_xor_sync(0xffffffffu, s, o);
    if (threadIdx.x == 0) gacc[row] = s;
}

// ------------------------------- launch --------------------------------------
extern "C" void kernel_launch(void* const* d_in, const int* in_sizes, int n_in,
                              void* d_out, int out_size)
{
    const float* x     = (const float*)d_in[0];
    const float* mask  = (const float*)d_in[1];
    const float* Wq    = (const float*)d_in[2];
    const float* bq    = (const float*)d_in[3];
    const float* Wk    = (const float*)d_in[4];
    const float* bk    = (const float*)d_in[5];
    const float* Wv    = (const float*)d_in[6];
    const float* bv    = (const float*)d_in[7];
    const float* Wo    = (const float*)d_in[8];
    const float* bo    = (const float*)d_in[9];
    const float* Wiq   = (const float*)d_in[10];
    const float* biq   = (const float*)d_in[11];
    const float* Wik   = (const float*)d_in[12];
    const float* bik   = (const float*)d_in[13];
    const float* embed = (const float*)d_in[14];
    const float* qw    = (const float*)d_in[15];
    const float* kw    = (const float*)d_in[16];
    float* out = (float*)d_out;

    float *qp,*kp,*vp,*attn,*feat,*iq,*ik,*gacc,*scores;
    cudaGetSymbolAddress((void**)&qp, g_qp);     cudaGetSymbolAddress((void**)&kp, g_kp);
    cudaGetSymbolAddress((void**)&vp, g_vp);
    cudaGetSymbolAddress((void**)&attn, g_attn); cudaGetSymbolAddress((void**)&feat, g_feat);
    cudaGetSymbolAddress((void**)&iq, g_iq);     cudaGetSymbolAddress((void**)&ik, g_ik);
    cudaGetSymbolAddress((void**)&gacc, g_gacc); cudaGetSymbolAddress((void**)&scores, g_scores);

    __nv_bfloat16 *qhg,*qlg,*khg,*klg,*vhg,*vlg;
    cudaGetSymbolAddress((void**)&qhg, g_qhg);   cudaGetSymbolAddress((void**)&qlg, g_qlg);
    cudaGetSymbolAddress((void**)&khg, g_khg);   cudaGetSymbolAddress((void**)&klg, g_klg);
    cudaGetSymbolAddress((void**)&vhg, g_vhg);   cudaGetSymbolAddress((void**)&vlg, g_vlg);

    __nv_bfloat16 *wqh,*wql,*wkh,*wkl,*wvh,*wvl,*wiqh,*wiql,*wikh,*wikl,*woh,*wol;
    __nv_bfloat16 *xh,*xl,*ah,*al,*fh,*fl,*iqh,*iql,*ikh,*ikl,*gth,*gtl;
    cudaGetSymbolAddress((void**)&wqh, g_wqh);   cudaGetSymbolAddress((void**)&wql, g_wql);
    cudaGetSymbolAddress((void**)&wkh, g_wkh);   cudaGetSymbolAddress((void**)&wkl, g_wkl);
    cudaGetSymbolAddress((void**)&wvh, g_wvh);   cudaGetSymbolAddress((void**)&wvl, g_wvl);
    cudaGetSymbolAddress((void**)&wiqh, g_wiqh); cudaGetSymbolAddress((void**)&wiql, g_wiql);
    cudaGetSymbolAddress((void**)&wikh, g_wikh); cudaGetSymbolAddress((void**)&wikl, g_wikl);
    cudaGetSymbolAddress((void**)&woh, g_woh);   cudaGetSymbolAddress((void**)&wol, g_wol);
    cudaGetSymbolAddress((void**)&xh, g_xh);     cudaGetSymbolAddress((void**)&xl, g_xl);
    cudaGetSymbolAddress((void**)&ah, g_ah);     cudaGetSymbolAddress((void**)&al, g_al);
    cudaGetSymbolAddress((void**)&fh, g_fh);     cudaGetSymbolAddress((void**)&fl, g_fl);
    cudaGetSymbolAddress((void**)&iqh, g_iqh);   cudaGetSymbolAddress((void**)&iql, g_iql);
    cudaGetSymbolAddress((void**)&ikh, g_ikh);   cudaGetSymbolAddress((void**)&ikl, g_ikl);
    cudaGetSymbolAddress((void**)&gth, g_gth);   cudaGetSymbolAddress((void**)&gtl, g_gtl);

    cudaFuncSetAttribute((const void*)mma_gemm_kernel,
                         cudaFuncAttributeMaxDynamicSharedMemorySize, TC_SMEM);
    cudaFuncSetAttribute((const void*)flash_mma_kernel,
                         cudaFuncAttributeMaxDynamicSharedMemorySize, FL_SMEM);

    dim3 wtg(32, 32);
    dim3 wtb(32, 8);
    const int N4 = MROWS * D_ / 4;
    const int SPLIT_BLOCKS = (N4 + 255) / 256;
    dim3 big_grid(D_/128, MROWS/128, 1);   // (8, 32)

    // weight prep (transpose + split)
    wt_split_kernel<<<wtg, wtb>>>(Wq,  wqh,  wql);
    wt_split_kernel<<<wtg, wtb>>>(Wk,  wkh,  wkl);
    wt_split_kernel<<<wtg, wtb>>>(Wv,  wvh,  wvl);
    wt_split_kernel<<<wtg, wtb>>>(Wiq, wiqh, wiql);
    wt_split_kernel<<<wtg, wtb>>>(Wik, wikh, wikl);
    wt_split_kernel<<<wtg, wtb>>>(Wo,  woh,  wol);

    // x split + QKV projections (3-pass split bf16)
    split_kernel<<<SPLIT_BLOCKS, 256>>>(x, xh, xl, N4, nullptr);
    mma_gemm_kernel<<<big_grid, 256, TC_SMEM>>>(xh, xl, wqh, wql, bq, qp, MROWS, D_, D_, 0, 0, 0, 1);
    mma_gemm_kernel<<<big_grid, 256, TC_SMEM>>>(xh, xl, wkh, wkl, bk, kp, MROWS, D_, D_, 0, 0, 0, 1);
    mma_gemm_kernel<<<big_grid, 256, TC_SMEM>>>(xh, xl, wvh, wvl, bv, vp, MROWS, D_, D_, 0, 0, 0, 1);

    // per-head RMS norm + split/scatter to grouped bf16 layout; attention
    rms_scatter_kernel<<<(MROWS*H_)/8, 256>>>(qp, kp, vp, qw, kw,
                                              qhg, qlg, khg, klg, vhg, vlg);
    flash_mma_kernel<<<dim3(SEQ/128, GH), 256, FL_SMEM>>>(qhg, qlg, khg, klg, vhg, vlg, attn);

    // instance features; splits
    feat_kernel<<<MROWS, 256>>>(mask, embed, feat);
    split_kernel<<<SPLIT_BLOCKS, 256>>>(attn, ah, al, N4, nullptr);
    split_kernel<<<SPLIT_BLOCKS, 256>>>(feat, fh, fl, N4, nullptr);

    // iq / ik projections (1-pass: feeds only the sigmoid-mean gate)
    mma_gemm_kernel<<<big_grid, 256, TC_SMEM>>>(ah, al, wiqh, wiql, biq, iq, MROWS, D_, D_, 0, 0, 0, 0);
    mma_gemm_kernel<<<big_grid, 256, TC_SMEM>>>(fh, fl, wikh, wikl, bik, ik, MROWS, D_, D_, 0, 0, 0, 0);

    // gate scores: per-batch iq @ ik^T (1-pass bf16)
    split_kernel<<<SPLIT_BLOCKS, 256>>>(iq, iqh, iql, N4, nullptr);
    split_kernel<<<SPLIT_BLOCKS, 256>>>(ik, ikh, ikl, N4, nullptr);
    mma_gemm_kernel<<<dim3(4, 4, 8), 256, TC_SMEM>>>(iqh, iql, ikh, ikl, nullptr, scores,
                                                     512, 512, D_,
                                                     (long)512*D_, (long)512*D_, (long)512*512, 0);
    sigred_kernel<<<512, dim3(32, 8)>>>(scores, gacc);

    // gated output projection (3-pass)
    split_kernel<<<SPLIT_BLOCKS, 256>>>(attn, gth, gtl, N4, gacc);
    mma_gemm_kernel<<<big_grid, 256, TC_SMEM>>>(gth, gtl, woh, wol, bo, out, MROWS, D_, D_, 0, 0, 0, 1);
}

// round 5
// speedup vs baseline: 3.5297x; 1.1721x over previous
#include <cuda_runtime.h>
#include <cuda_bf16.h>
#include <math.h>
#include <stdint.h>

// Problem constants
#define B_    8
#define N_    512
#define D_    1024
#define H_    16
#define HD_   64
#define NI_   4
#define G_    2
#define MROWS (B_*N_)      // 4096
#define SEQ   (NI_*N_)     // 2048
#define GH    (G_*H_)      // 32
#define SCALE 0.125f
#define S2    0.0078125f   // SCALE / H

// ---------------- scratch (device globals) -----------------------------------
static __device__ float g_qp[MROWS*D_];
static __device__ float g_kp[MROWS*D_];
static __device__ float g_vp[MROWS*D_];
static __device__ float g_gacc[MROWS];

// attention operand buffers: bf16 hi/lo, grouped layout [GH, SEQ, HD]
#define AELEMS (GH*SEQ*HD_)
static __device__ __align__(256) __nv_bfloat16 g_qhg[AELEMS], g_qlg[AELEMS];
static __device__ __align__(256) __nv_bfloat16 g_khg[AELEMS], g_klg[AELEMS];
static __device__ __align__(256) __nv_bfloat16 g_vhg[AELEMS], g_vlg[AELEMS];

// split-bf16 weight (transposed [N,K]) and activation buffers
static __device__ __align__(256) __nv_bfloat16 g_wqh[D_*D_], g_wql[D_*D_];
static __device__ __align__(256) __nv_bfloat16 g_wkh[D_*D_], g_wkl[D_*D_];
static __device__ __align__(256) __nv_bfloat16 g_wvh[D_*D_], g_wvl[D_*D_];
static __device__ __align__(256) __nv_bfloat16 g_wiqh[D_*D_], g_wiql[D_*D_];
static __device__ __align__(256) __nv_bfloat16 g_wikh[D_*D_], g_wikl[D_*D_];
static __device__ __align__(256) __nv_bfloat16 g_woh[D_*D_], g_wol[D_*D_];
static __device__ __align__(256) __nv_bfloat16 g_xh[MROWS*D_],  g_xl[MROWS*D_];
static __device__ __align__(256) __nv_bfloat16 g_ah[MROWS*D_],  g_al[MROWS*D_];   // attn hi/lo
static __device__ __align__(256) __nv_bfloat16 g_fh[MROWS*D_],  g_fl[MROWS*D_];
static __device__ __align__(256) __nv_bfloat16 g_iqh[MROWS*D_];
static __device__ __align__(256) __nv_bfloat16 g_ikh[MROWS*D_];

// ---------------- PTX helpers --------------------------------------------------
__device__ __forceinline__ uint32_t smem_u32(const void* p) {
    uint32_t a;
    asm("{ .reg .u64 t; cvta.to.shared.u64 t, %1; cvt.u32.u64 %0, t; }"
        : "=r"(a) : "l"(p));
    return a;
}

#define LDSM4(r, addr) \
    asm volatile("ldmatrix.sync.aligned.m8n8.x4.shared.b16 {%0,%1,%2,%3}, [%4];" \
        : "=r"((r)[0]), "=r"((r)[1]), "=r"((r)[2]), "=r"((r)[3]) : "r"(addr))

#define LDSM4T(r, addr) \
    asm volatile("ldmatrix.sync.aligned.m8n8.x4.trans.shared.b16 {%0,%1,%2,%3}, [%4];" \
        : "=r"((r)[0]), "=r"((r)[1]), "=r"((r)[2]), "=r"((r)[3]) : "r"(addr))

#define MMA16816(d, a, bv0, bv1) \
    asm volatile("mma.sync.aligned.m16n8k16.row.col.f32.bf16.bf16.f32 " \
        "{%0,%1,%2,%3}, {%4,%5,%6,%7}, {%8,%9}, {%0,%1,%2,%3};" \
        : "+f"((d)[0]), "+f"((d)[1]), "+f"((d)[2]), "+f"((d)[3]) \
        : "r"((a)[0]), "r"((a)[1]), "r"((a)[2]), "r"((a)[3]), "r"(bv0), "r"(bv1))

#define CP_ASYNC16(dst, src) \
    asm volatile("cp.async.cg.shared.global [%0], [%1], 16;" \
        :: "r"(dst), "l"(__cvta_generic_to_global(src)) : "memory")
#define CP_COMMIT() asm volatile("cp.async.commit_group;" ::: "memory")
#define CP_WAIT(n)  asm volatile("cp.async.wait_group %0;" :: "n"(n) : "memory")

__device__ __forceinline__ uint32_t packbf(float a, float b) {
    // low half = bf16(a), high half = bf16(b)
    uint32_t d;
    asm("cvt.rn.bf16x2.f32 %0, %1, %2;" : "=r"(d) : "f"(b), "f"(a));
    return d;
}
__device__ __forceinline__ float bflo(uint32_t v) { return __uint_as_float(v << 16); }
__device__ __forceinline__ float bfhi(uint32_t v) { return __uint_as_float(v & 0xffff0000u); }

// ---------------- HMMA split-bf16 GEMM ----------------------------------------
// C[z] = A[z] @ B[z]^T + bias.
// three_pass: 1 -> AhBh + AhBl + AlBh (interleaved); 0 -> AhBh only (skips lo loads)
// out_mode: 0 fp32 C+bias; 1 bf16-hi Cbf (+bias); 2 fp32 gate-scaled C = (1+grow[r]/512)*acc + bias;
//           3 sigmoid row-sum atomics into gout (no C write)
#define TC_SMEM (2*4*16384)   // 131072
__global__ __launch_bounds__(256, 1)
void mma_gemm_kernel(const __nv_bfloat16* __restrict__ Ahp, const __nv_bfloat16* __restrict__ Alp,
                     const __nv_bfloat16* __restrict__ Bhp, const __nv_bfloat16* __restrict__ Blp,
                     const float* __restrict__ bias, float* __restrict__ C,
                     __nv_bfloat16* __restrict__ Cbf,
                     const float* __restrict__ grow, float* __restrict__ gout,
                     int M, int N, int K, long sA, long sB, long sC,
                     int three_pass, int out_mode)
{
    extern __shared__ char smem[];
    uint32_t sb = smem_u32(smem);
    int tid = threadIdx.x, wid = tid >> 5, lane = tid & 31;
    int m0 = blockIdx.y * 128, n0 = blockIdx.x * 128;
    long zb = blockIdx.z;
    const __nv_bfloat16* Ah = Ahp + zb * sA;
    const __nv_bfloat16* Al = three_pass ? (Alp + zb * sA) : Ahp;
    const __nv_bfloat16* Bh = Bhp + zb * sB;
    const __nv_bfloat16* Bl = three_pass ? (Blp + zb * sB) : Bhp;

    const int nsteps = K / 64;

    auto issue = [&](int step, int stage) {
        uint32_t stb = sb + stage * 65536;
        int k0 = step * 64;
        if (three_pass) {
#pragma unroll
            for (int i = 0; i < 16; i++) {
                int c = i * 256 + tid;
                int tile = c >> 10;
                int w = c & 1023;
                int row = w >> 3, ch = w & 7;
                const __nv_bfloat16* src;
                int gr;
                if      (tile == 0) { src = Ah; gr = m0 + row; }
                else if (tile == 1) { src = Al; gr = m0 + row; }
                else if (tile == 2) { src = Bh; gr = n0 + row; }
                else                { src = Bl; gr = n0 + row; }
                const __nv_bfloat16* gp = src + (long)gr * K + k0 + ch * 8;
                uint32_t dst = stb + tile * 16384 + row * 128 + ((ch ^ (row & 7)) << 4);
                CP_ASYNC16(dst, gp);
            }
        } else {
#pragma unroll
            for (int i = 0; i < 8; i++) {
                int c = i * 256 + tid;
                int half = c >> 10;           // 0 = Ah, 1 = Bh
                int w = c & 1023;
                int row = w >> 3, ch = w & 7;
                const __nv_bfloat16* src = half ? Bh : Ah;
                int gr = (half ? n0 : m0) + row;
                const __nv_bfloat16* gp = src + (long)gr * K + k0 + ch * 8;
                uint32_t dst = stb + half * 32768 + row * 128 + ((ch ^ (row & 7)) << 4);
                CP_ASYNC16(dst, gp);
            }
        }
        CP_COMMIT();
    };

    int mbase = (wid >> 2) * 64;
    int nbase = (wid & 3) * 32;

    float acc[4][4][4];
#pragma unroll
    for (int mt = 0; mt < 4; mt++)
#pragma unroll
        for (int nt = 0; nt < 4; nt++)
#pragma unroll
            for (int e = 0; e < 4; e++) acc[mt][nt][e] = 0.f;

    issue(0, 0);
    if (nsteps > 1) issue(1, 1);

    for (int step = 0; step < nsteps; step++) {
        if (step + 1 < nsteps) { CP_WAIT(1); } else { CP_WAIT(0); }
        __syncthreads();

        uint32_t stb = sb + (step & 1) * 65536;
#pragma unroll
        for (int k16 = 0; k16 < 4; k16++) {
            uint32_t ahf[4][4], alf[4][4], bhf[2][4], blf[2][4];
            int arow = lane & 15;
            int ach = 2 * k16 + (lane >> 4);
#pragma unroll
            for (int mt = 0; mt < 4; mt++) {
                int row = mbase + mt * 16 + arow;
                uint32_t ad = stb + row * 128 + ((ach ^ (row & 7)) << 4);
                LDSM4(ahf[mt], ad);
                if (three_pass) LDSM4(alf[mt], ad + 16384);
            }
            int brow = (lane & 7) + ((lane >> 4) & 1) * 8;
            int bch = 2 * k16 + ((lane >> 3) & 1);
#pragma unroll
            for (int j = 0; j < 2; j++) {
                int row = nbase + j * 16 + brow;
                uint32_t bd = stb + 32768 + row * 128 + ((bch ^ (row & 7)) << 4);
                LDSM4(bhf[j], bd);
                if (three_pass) LDSM4(blf[j], bd + 16384);
            }
            // pass 0: hi*hi — accumulator dependency distance 16
#pragma unroll
            for (int mt = 0; mt < 4; mt++)
#pragma unroll
                for (int nt = 0; nt < 4; nt++) {
                    int j = nt >> 1, p = (nt & 1) * 2;
                    MMA16816(acc[mt][nt], ahf[mt], bhf[j][p], bhf[j][p+1]);
                }
            if (three_pass) {
#pragma unroll
                for (int mt = 0; mt < 4; mt++)
#pragma unroll
                    for (int nt = 0; nt < 4; nt++) {
                        int j = nt >> 1, p = (nt & 1) * 2;
                        MMA16816(acc[mt][nt], ahf[mt], blf[j][p], blf[j][p+1]);
                    }
#pragma unroll
                for (int mt = 0; mt < 4; mt++)
#pragma unroll
                    for (int nt = 0; nt < 4; nt++) {
                        int j = nt >> 1, p = (nt & 1) * 2;
                        MMA16816(acc[mt][nt], alf[mt], bhf[j][p], bhf[j][p+1]);
                    }
            }
        }
        __syncthreads();
        if (step + 2 < nsteps) issue(step + 2, step & 1);
    }

    // ------------------------------ epilogues ---------------------------------
    if (out_mode == 3) {
        // sigmoid row-sum -> atomic add into gout[zb*512 + r]
#pragma unroll
        for (int mt = 0; mt < 4; mt++) {
            int r0 = m0 + mbase + mt * 16 + (lane >> 2);
            float ps0 = 0.f, ps1 = 0.f;
#pragma unroll
            for (int nt = 0; nt < 4; nt++) {
                ps0 += 1.0f / (1.0f + __expf(-acc[mt][nt][0] * S2));
                ps0 += 1.0f / (1.0f + __expf(-acc[mt][nt][1] * S2));
                ps1 += 1.0f / (1.0f + __expf(-acc[mt][nt][2] * S2));
                ps1 += 1.0f / (1.0f + __expf(-acc[mt][nt][3] * S2));
            }
            ps0 += __shfl_xor_sync(0xffffffffu, ps0, 1, 4);
            ps0 += __shfl_xor_sync(0xffffffffu, ps0, 2, 4);
            ps1 += __shfl_xor_sync(0xffffffffu, ps1, 1, 4);
            ps1 += __shfl_xor_sync(0xffffffffu, ps1, 2, 4);
            if ((lane & 3) == 0) {
                atomicAdd(&gout[zb * 512 + r0], ps0);
                atomicAdd(&gout[zb * 512 + r0 + 8], ps1);
            }
        }
        return;
    }

#pragma unroll
    for (int mt = 0; mt < 4; mt++) {
        int r0 = m0 + mbase + mt * 16 + (lane >> 2);
        float g0 = 1.f, g1 = 1.f;
        if (out_mode == 2) {
            g0 = 1.0f + grow[r0] * (1.0f/512.0f);
            g1 = 1.0f + grow[r0 + 8] * (1.0f/512.0f);
        }
#pragma unroll
        for (int nt = 0; nt < 4; nt++) {
            int c = n0 + nbase + nt * 8 + 2 * (lane & 3);
            float b0 = 0.f, b1 = 0.f;
            if (bias) { b0 = bias[c]; b1 = bias[c + 1]; }
            float v00 = acc[mt][nt][0] * g0 + b0, v01 = acc[mt][nt][1] * g0 + b1;
            float v10 = acc[mt][nt][2] * g1 + b0, v11 = acc[mt][nt][3] * g1 + b1;
            if (out_mode == 1) {
                *(uint32_t*)&Cbf[(long)r0 * N + c]       = packbf(v00, v01);
                *(uint32_t*)&Cbf[(long)(r0 + 8) * N + c] = packbf(v10, v11);
            } else {
                float* Cc = C + zb * sC;
                float2 w0; w0.x = v00; w0.y = v01;
                *(float2*)&Cc[(long)r0 * N + c] = w0;
                float2 w1; w1.x = v10; w1.y = v11;
                *(float2*)&Cc[(long)(r0 + 8) * N + c] = w1;
            }
        }
    }
}

// ---------------- weight transpose + split to bf16 (64x64 tiles) -------------
__global__ __launch_bounds__(256) void wt_split_kernel(
    const float* __restrict__ W, __nv_bfloat16* __restrict__ Th, __nv_bfloat16* __restrict__ Tl)
{
    __shared__ float t[64][65];
    int n0 = blockIdx.x * 64, k0 = blockIdx.y * 64;
    int tid = threadIdx.x;
#pragma unroll
    for (int it = 0; it < 4; it++) {
        int row = (tid >> 4) + it * 16;
        int c4 = (tid & 15) * 4;
        float4 v = *(const float4*)&W[(long)(k0 + row) * D_ + n0 + c4];
        t[row][c4+0] = v.x; t[row][c4+1] = v.y; t[row][c4+2] = v.z; t[row][c4+3] = v.w;
    }
    __syncthreads();
    int n = tid >> 2, kc = (tid & 3) * 16;
    uint32_t hb[8], lb[8];
#pragma unroll
    for (int j = 0; j < 16; j += 2) {
        float f0 = t[kc + j][n], f1 = t[kc + j + 1][n];
        uint32_t h = packbf(f0, f1);
        hb[j >> 1] = h;
        lb[j >> 1] = packbf(f0 - bflo(h), f1 - bfhi(h));
    }
    long obase = (long)(n0 + n) * D_ + k0 + kc;
    *(uint4*)&Th[obase]     = make_uint4(hb[0], hb[1], hb[2], hb[3]);
    *(uint4*)&Th[obase + 8] = make_uint4(hb[4], hb[5], hb[6], hb[7]);
    *(uint4*)&Tl[obase]     = make_uint4(lb[0], lb[1], lb[2], lb[3]);
    *(uint4*)&Tl[obase + 8] = make_uint4(lb[4], lb[5], lb[6], lb[7]);
}

// ---------------- activation split ---------------------------------------------
__global__ __launch_bounds__(256) void split_kernel(
    const float* __restrict__ src, __nv_bfloat16* __restrict__ h,
    __nv_bfloat16* __restrict__ l, int n4)
{
    int i = blockIdx.x * 256 + threadIdx.x;
    if (i >= n4) return;
    float4 f = ((const float4*)src)[i];
    uint32_t h0 = packbf(f.x, f.y), h1 = packbf(f.z, f.w);
    ((uint32_t*)h)[i*2+0] = h0;
    ((uint32_t*)h)[i*2+1] = h1;
    ((uint32_t*)l)[i*2+0] = packbf(f.x - bflo(h0), f.y - bfhi(h0));
    ((uint32_t*)l)[i*2+1] = packbf(f.z - bflo(h1), f.w - bfhi(h1));
}

// ------- RMS-norm (q,k) + split to bf16 hi/lo, scatter into [GH, SEQ, HD] ----
__global__ __launch_bounds__(256) void rms_scatter_kernel(
    const float* __restrict__ qp, const float* __restrict__ kp,
    const float* __restrict__ vp,
    const float* __restrict__ qw, const float* __restrict__ kw,
    __nv_bfloat16* __restrict__ qh, __nv_bfloat16* __restrict__ ql,
    __nv_bfloat16* __restrict__ kh, __nv_bfloat16* __restrict__ kl,
    __nv_bfloat16* __restrict__ vh, __nv_bfloat16* __restrict__ vl)
{
    int wid  = (blockIdx.x * 256 + threadIdx.x) >> 5;
    int lane = threadIdx.x & 31;
    int h  = wid & 15;
    int bn = wid >> 4;
    int b  = bn >> 9;
    long ibase = (long)bn * D_ + h * HD_;
    int g = b >> 2, inst = b & 3;
    int n = bn & 511;
    long obase = (((long)(g*16 + h)) * SEQ + inst*512 + n) * HD_;

    auto emit = [&](float v, __nv_bfloat16* ph, __nv_bfloat16* pl, long off) {
        __nv_bfloat16 hb = __float2bfloat16(v);
        ph[off] = hb;
        pl[off] = __float2bfloat16(v - __bfloat162float(hb));
    };
    {
        float v0 = qp[ibase + lane], v1 = qp[ibase + lane + 32];
        float ss = v0*v0 + v1*v1;
#pragma unroll
        for (int off = 16; off; off >>= 1) ss += __shfl_xor_sync(0xffffffffu, ss, off);
        float sc = rsqrtf(ss * (1.0f/64.0f) + 1e-6f) * SCALE;
        emit(v0 * sc * qw[lane],      qh, ql, obase + lane);
        emit(v1 * sc * qw[lane + 32], qh, ql, obase + lane + 32);
    }
    {
        float v0 = kp[ibase + lane], v1 = kp[ibase + lane + 32];
        float ss = v0*v0 + v1*v1;
#pragma unroll
        for (int off = 16; off; off >>= 1) ss += __shfl_xor_sync(0xffffffffu, ss, off);
        float sc = rsqrtf(ss * (1.0f/64.0f) + 1e-6f);
        emit(v0 * sc * kw[lane],      kh, kl, obase + lane);
        emit(v1 * sc * kw[lane + 32], kh, kl, obase + lane + 32);
    }
    emit(vp[ibase + lane],      vh, vl, obase + lane);
    emit(vp[ibase + lane + 32], vh, vl, obase + lane + 32);
}

// ---------------- flash attention via mma.sync (split-bf16 3-pass) -----------
// grid (16 q-tiles of 128, 32 gh), 256 threads. Writes attn bf16 hi/lo directly.
#define FL_SMEM (2*65536 + 32768)
__global__ __launch_bounds__(256, 1)
void flash_mma_kernel(const __nv_bfloat16* __restrict__ Qh_, const __nv_bfloat16* __restrict__ Ql_,
                      const __nv_bfloat16* __restrict__ Kh_, const __nv_bfloat16* __restrict__ Kl_,
                      const __nv_bfloat16* __restrict__ Vh_, const __nv_bfloat16* __restrict__ Vl_,
                      __nv_bfloat16* __restrict__ Oh, __nv_bfloat16* __restrict__ Ol)
{
    extern __shared__ char smem[];
    uint32_t sb = smem_u32(smem);
    int tid = threadIdx.x, wid = tid >> 5, lane = tid & 31;
    int qt = blockIdx.x, gh = blockIdx.y;
    long ghoff = (long)gh * SEQ * HD_;
    const __nv_bfloat16* Qh = Qh_ + ghoff + (long)qt * 128 * HD_;
    const __nv_bfloat16* Ql = Ql_ + ghoff + (long)qt * 128 * HD_;
    const __nv_bfloat16* Kh = Kh_ + ghoff;
    const __nv_bfloat16* Kl = Kl_ + ghoff;
    const __nv_bfloat16* Vh = Vh_ + ghoff;
    const __nv_bfloat16* Vl = Vl_ + ghoff;

    const uint32_t QOFF = 131072;

    {
#pragma unroll
        for (int i = 0; i < 8; i++) {
            int c = i * 256 + tid;
            int arr = c >> 10, w = c & 1023, row = w >> 3, ch = w & 7;
            const __nv_bfloat16* src = (arr ? Ql : Qh) + (long)row * 64 + ch * 8;
            uint32_t dst = sb + QOFF + arr * 16384 + row * 128 + ((ch ^ (row & 7)) << 4);
            CP_ASYNC16(dst, src);
        }
        CP_COMMIT();
    }

    auto issueKV = [&](int it, int stage) {
        uint32_t stb = sb + stage * 65536;
#pragma unroll
        for (int i = 0; i < 16; i++) {
            int c = i * 256 + tid;
            int arr = c >> 10, w = c & 1023, row = w >> 3, ch = w & 7;
            const __nv_bfloat16* src;
            if      (arr == 0) src = Kh;
            else if (arr == 1) src = Kl;
            else if (arr == 2) src = Vh;
            else               src = Vl;
            src += (long)(it * 128 + row) * 64 + ch * 8;
            uint32_t dst = stb + arr * 16384 + row * 128 + ((ch ^ (row & 7)) << 4);
            CP_ASYNC16(dst, src);
        }
        CP_COMMIT();
    };

    issueKV(0, 0);
    issueKV(1, 1);
    CP_WAIT(1);
    __syncthreads();

    uint32_t qhf[4][4], qlf[4][4];
    {
        int arow = lane & 15;
#pragma unroll
        for (int kt = 0; kt < 4; kt++) {
            int row = wid * 16 + arow;
            int ach = 2 * kt + (lane >> 4);
            uint32_t ad = sb + QOFF + row * 128 + ((ach ^ (row & 7)) << 4);
            LDSM4(qhf[kt], ad);
            LDSM4(qlf[kt], ad + 16384);
        }
    }

    float o[8][4];
#pragma unroll
    for (int nt = 0; nt < 8; nt++)
#pragma unroll
        for (int e = 0; e < 4; e++) o[nt][e] = 0.f;
    float m0 = -1e30f, m1 = -1e30f, lp0 = 0.f, lp1 = 0.f;

    for (int it = 0; it < 16; it++) {
        if (it > 0) {
            if (it < 15) { CP_WAIT(1); } else { CP_WAIT(0); }
            __syncthreads();
        }
        uint32_t stb = sb + (it & 1) * 65536;

        // ---- S = Q @ K^T (3-pass, jj processed in pairs, dep distance 4) ----
        float s[16][4];
#pragma unroll
        for (int t = 0; t < 16; t++)
#pragma unroll
            for (int e = 0; e < 4; e++) s[t][e] = 0.f;

        int brow = (lane & 7) + ((lane >> 4) & 1) * 8;
#pragma unroll
        for (int kt = 0; kt < 4; kt++) {
            int bch = 2 * kt + ((lane >> 3) & 1);
#pragma unroll
            for (int jp = 0; jp < 4; jp++) {
                uint32_t khf[2][4], klf[2][4];
#pragma unroll
                for (int j = 0; j < 2; j++) {
                    int row = (2 * jp + j) * 16 + brow;
                    uint32_t bd = stb + row * 128 + ((bch ^ (row & 7)) << 4);
                    LDSM4(khf[j], bd);
                    LDSM4(klf[j], bd + 16384);
                }
                int t0 = 4 * jp;
                MMA16816(s[t0+0], qhf[kt], khf[0][0], khf[0][1]);
                MMA16816(s[t0+1], qhf[kt], khf[0][2], khf[0][3]);
                MMA16816(s[t0+2], qhf[kt], khf[1][0], khf[1][1]);
                MMA16816(s[t0+3], qhf[kt], khf[1][2], khf[1][3]);
                MMA16816(s[t0+0], qhf[kt], klf[0][0], klf[0][1]);
                MMA16816(s[t0+1], qhf[kt], klf[0][2], klf[0][3]);
                MMA16816(s[t0+2], qhf[kt], klf[1][0], klf[1][1]);
                MMA16816(s[t0+3], qhf[kt], klf[1][2], klf[1][3]);
                MMA16816(s[t0+0], qlf[kt], khf[0][0], khf[0][1]);
                MMA16816(s[t0+1], qlf[kt], khf[0][2], khf[0][3]);
                MMA16816(s[t0+2], qlf[kt], khf[1][0], khf[1][1]);
                MMA16816(s[t0+3], qlf[kt], khf[1][2], khf[1][3]);
            }
        }

        // ---- online softmax ----
        float t0 = -1e30f, t1 = -1e30f;
#pragma unroll
        for (int t = 0; t < 16; t++) {
            t0 = fmaxf(t0, fmaxf(s[t][0], s[t][1]));
            t1 = fmaxf(t1, fmaxf(s[t][2], s[t][3]));
        }
        t0 = fmaxf(t0, __shfl_xor_sync(0xffffffffu, t0, 1, 4));
        t0 = fmaxf(t0, __shfl_xor_sync(0xffffffffu, t0, 2, 4));
        t1 = fmaxf(t1, __shfl_xor_sync(0xffffffffu, t1, 1, 4));
        t1 = fmaxf(t1, __shfl_xor_sync(0xffffffffu, t1, 2, 4));
        float mn0 = fmaxf(m0, t0), mn1 = fmaxf(m1, t1);
        float c0 = __expf(m0 - mn0), c1 = __expf(m1 - mn1);
        m0 = mn0; m1 = mn1;
        lp0 *= c0; lp1 *= c1;
#pragma unroll
        for (int nt = 0; nt < 8; nt++) {
            o[nt][0] *= c0; o[nt][1] *= c0;
            o[nt][2] *= c1; o[nt][3] *= c1;
        }
#pragma unroll
        for (int t = 0; t < 16; t++) {
            s[t][0] = __expf(s[t][0] - m0);
            s[t][1] = __expf(s[t][1] - m0);
            s[t][2] = __expf(s[t][2] - m1);
            s[t][3] = __expf(s[t][3] - m1);
            lp0 += s[t][0] + s[t][1];
            lp1 += s[t][2] + s[t][3];
        }

        // ---- O += P @ V (3-pass, nt4 pairs, dep distance 4) ----
        int vrow = lane & 15;
#pragma unroll
        for (int kt = 0; kt < 8; kt++) {
            uint32_t pha[4], pla[4];
#pragma unroll
            for (int q = 0; q < 2; q++) {
                float a0 = s[2*kt + q][0], a1 = s[2*kt + q][1];
                float a2 = s[2*kt + q][2], a3 = s[2*kt + q][3];
                uint32_t h0 = packbf(a0, a1);
                uint32_t h1 = packbf(a2, a3);
                pha[2*q]   = h0;
                pha[2*q+1] = h1;
                pla[2*q]   = packbf(a0 - bflo(h0), a1 - bfhi(h0));
                pla[2*q+1] = packbf(a2 - bflo(h1), a3 - bfhi(h1));
            }
            int row = kt * 16 + vrow;
#pragma unroll
            for (int np = 0; np < 2; np++) {
                uint32_t vhf[2][4], vlf[2][4];
#pragma unroll
                for (int j = 0; j < 2; j++) {
                    int ch = 2 * (2 * np + j) + (lane >> 4);
                    uint32_t vd = stb + 32768 + row * 128 + ((ch ^ (row & 7)) << 4);
                    LDSM4T(vhf[j], vd);
                    LDSM4T(vlf[j], vd + 16384);
                }
                int ob = 4 * np;
                MMA16816(o[ob+0], pha, vhf[0][0], vhf[0][1]);
                MMA16816(o[ob+1], pha, vhf[0][2], vhf[0][3]);
                MMA16816(o[ob+2], pha, vhf[1][0], vhf[1][1]);
                MMA16816(o[ob+3], pha, vhf[1][2], vhf[1][3]);
                MMA16816(o[ob+0], pha, vlf[0][0], vlf[0][1]);
                MMA16816(o[ob+1], pha, vlf[0][2], vlf[0][3]);
                MMA16816(o[ob+2], pha, vlf[1][0], vlf[1][1]);
                MMA16816(o[ob+3], pha, vlf[1][2], vlf[1][3]);
                MMA16816(o[ob+0], pla, vhf[0][0], vhf[0][1]);
                MMA16816(o[ob+1], pla, vhf[0][2], vhf[0][3]);
                MMA16816(o[ob+2], pla, vhf[1][0], vhf[1][1]);
                MMA16816(o[ob+3], pla, vhf[1][2], vhf[1][3]);
            }
        }

        __syncthreads();
        if (it + 2 < 16) issueKV(it + 2, it & 1);
    }

    // ---- epilogue: normalize, split to bf16 hi/lo, scatter to [B*N, D] ----
    lp0 += __shfl_xor_sync(0xffffffffu, lp0, 1, 4);
    lp0 += __shfl_xor_sync(0xffffffffu, lp0, 2, 4);
    lp1 += __shfl_xor_sync(0xffffffffu, lp1, 1, 4);
    lp1 += __shfl_xor_sync(0xffffffffu, lp1, 2, 4);
    float inv0 = 1.0f / lp0, inv1 = 1.0f / lp1;

    int g = gh >> 4, h = gh & 15;
#pragma unroll
    for (int e = 0; e < 2; e++) {
        int r = qt * 128 + wid * 16 + (lane >> 2) + 8 * e;
        int inst = r >> 9, n = r & 511;
        int b = g * 4 + inst;
        float inv = e ? inv1 : inv0;
        long base = ((long)(b * 512 + n)) * D_ + h * HD_;
#pragma unroll
        for (int nt = 0; nt < 8; nt++) {
            float v0 = o[nt][2*e] * inv, v1 = o[nt][2*e+1] * inv;
            uint32_t hp = packbf(v0, v1);
            uint32_t lp = packbf(v0 - bflo(hp), v1 - bfhi(hp));
            long idx = base + nt * 8 + 2 * (lane & 3);
            *(uint32_t*)&Oh[idx] = hp;
            *(uint32_t*)&Ol[idx] = lp;
        }
    }
}

// ---------------- instance feature -> bf16 hi/lo directly --------------------
__global__ __launch_bounds__(256) void feat_kernel(
    const float* __restrict__ mask, const float* __restrict__ embed,
    __nv_bfloat16* __restrict__ fh, __nv_bfloat16* __restrict__ fl)
{
    int row = blockIdx.x;
    float m0 = mask[row*4+0], m1 = mask[row*4+1];
    float m2 = mask[row*4+2], m3 = mask[row*4+3];
    for (int c = threadIdx.x * 2; c < D_; c += 512) {
        float f0 = m0*embed[c]   + m1*embed[D_ + c]   + m2*embed[2*D_ + c]   + m3*embed[3*D_ + c];
        float f1 = m0*embed[c+1] + m1*embed[D_ + c+1] + m2*embed[2*D_ + c+1] + m3*embed[3*D_ + c+1];
        uint32_t h = packbf(f0, f1);
        *(uint32_t*)&fh[(long)row*D_ + c] = h;
        *(uint32_t*)&fl[(long)row*D_ + c] = packbf(f0 - bflo(h), f1 - bfhi(h));
    }
}

// ---------------- zero kernel -------------------------------------------------
__global__ void zero_kernel(float* __restrict__ p, int n)
{
    int i = blockIdx.x * blockDim.x + threadIdx.x;
    if (i < n) p[i] = 0.f;
}

// ------------------------------- launch --------------------------------------
extern "C" void kernel_launch(void* const* d_in, const int* in_sizes, int n_in,
                              void* d_out, int out_size)
{
    const float* x     = (const float*)d_in[0];
    const float* mask  = (const float*)d_in[1];
    const float* Wq    = (const float*)d_in[2];
    const float* bq    = (const float*)d_in[3];
    const float* Wk    = (const float*)d_in[4];
    const float* bk    = (const float*)d_in[5];
    const float* Wv    = (const float*)d_in[6];
    const float* bv    = (const float*)d_in[7];
    const float* Wo    = (const float*)d_in[8];
    const float* bo    = (const float*)d_in[9];
    const float* Wiq   = (const float*)d_in[10];
    const float* biq   = (const float*)d_in[11];
    const float* Wik   = (const float*)d_in[12];
    const float* bik   = (const float*)d_in[13];
    const float* embed = (const float*)d_in[14];
    const float* qw    = (const float*)d_in[15];
    const float* kw    = (const float*)d_in[16];
    float* out = (float*)d_out;

    float *qp,*kp,*vp,*gacc;
    cudaGetSymbolAddress((void**)&qp, g_qp);     cudaGetSymbolAddress((void**)&kp, g_kp);
    cudaGetSymbolAddress((void**)&vp, g_vp);     cudaGetSymbolAddress((void**)&gacc, g_gacc);

    __nv_bfloat16 *qhg,*qlg,*khg,*klg,*vhg,*vlg;
    cudaGetSymbolAddress((void**)&qhg, g_qhg);   cudaGetSymbolAddress((void**)&qlg, g_qlg);
    cudaGetSymbolAddress((void**)&khg, g_khg);   cudaGetSymbolAddress((void**)&klg, g_klg);
    cudaGetSymbolAddress((void**)&vhg, g_vhg);   cudaGetSymbolAddress((void**)&vlg, g_vlg);

    __nv_bfloat16 *wqh,*wql,*wkh,*wkl,*wvh,*wvl,*wiqh,*wiql,*wikh,*wikl,*woh,*wol;
    __nv_bfloat16 *xh,*xl,*ah,*al,*fh,*fl,*iqh,*ikh;
    cudaGetSymbolAddress((void**)&wqh, g_wqh);   cudaGetSymbolAddress((void**)&wql, g_wql);
    cudaGetSymbolAddress((void**)&wkh, g_wkh);   cudaGetSymbolAddress((void**)&wkl, g_wkl);
    cudaGetSymbolAddress((void**)&wvh, g_wvh);   cudaGetSymbolAddress((void**)&wvl, g_wvl);
    cudaGetSymbolAddress((void**)&wiqh, g_wiqh); cudaGetSymbolAddress((void**)&wiql, g_wiql);
    cudaGetSymbolAddress((void**)&wikh, g_wikh); cudaGetSymbolAddress((void**)&wikl, g_wikl);
    cudaGetSymbolAddress((void**)&woh, g_woh);   cudaGetSymbolAddress((void**)&wol, g_wol);
    cudaGetSymbolAddress((void**)&xh, g_xh);     cudaGetSymbolAddress((void**)&xl, g_xl);
    cudaGetSymbolAddress((void**)&ah, g_ah);     cudaGetSymbolAddress((void**)&al, g_al);
    cudaGetSymbolAddress((void**)&fh, g_fh);     cudaGetSymbolAddress((void**)&fl, g_fl);
    cudaGetSymbolAddress((void**)&iqh, g_iqh);   cudaGetSymbolAddress((void**)&ikh, g_ikh);

    cudaFuncSetAttribute((const void*)mma_gemm_kernel,
                         cudaFuncAttributeMaxDynamicSharedMemorySize, TC_SMEM);
    cudaFuncSetAttribute((const void*)flash_mma_kernel,
                         cudaFuncAttributeMaxDynamicSharedMemorySize, FL_SMEM);

    dim3 wtg(16, 16);
    const int N4 = MROWS * D_ / 4;
    const int SPLIT_BLOCKS = (N4 + 255) / 256;
    dim3 big_grid(D_/128, MROWS/128, 1);   // (8, 32)

    // weight prep
    wt_split_kernel<<<wtg, 256>>>(Wq,  wqh,  wql);
    wt_split_kernel<<<wtg, 256>>>(Wk,  wkh,  wkl);
    wt_split_kernel<<<wtg, 256>>>(Wv,  wvh,  wvl);
    wt_split_kernel<<<wtg, 256>>>(Wiq, wiqh, wiql);
    wt_split_kernel<<<wtg, 256>>>(Wik, wikh, wikl);
    wt_split_kernel<<<wtg, 256>>>(Wo,  woh,  wol);

    // x split + QKV projections (3-pass)
    split_kernel<<<SPLIT_BLOCKS, 256>>>(x, xh, xl, N4);
    mma_gemm_kernel<<<big_grid, 256, TC_SMEM>>>(xh, xl, wqh, wql, bq, qp, nullptr, nullptr, nullptr,
                                                MROWS, D_, D_, 0, 0, 0, 1, 0);
    mma_gemm_kernel<<<big_grid, 256, TC_SMEM>>>(xh, xl, wkh, wkl, bk, kp, nullptr, nullptr, nullptr,
                                                MROWS, D_, D_, 0, 0, 0, 1, 0);
    mma_gemm_kernel<<<big_grid, 256, TC_SMEM>>>(xh, xl, wvh, wvl, bv, vp, nullptr, nullptr, nullptr,
                                                MROWS, D_, D_, 0, 0, 0, 1, 0);

    // per-head RMS norm + split/scatter; attention (writes ah/al directly)
    rms_scatter_kernel<<<(MROWS*H_)/8, 256>>>(qp, kp, vp, qw, kw,
                                              qhg, qlg, khg, klg, vhg, vlg);
    flash_mma_kernel<<<dim3(SEQ/128, GH), 256, FL_SMEM>>>(qhg, qlg, khg, klg, vhg, vlg, ah, al);

    // instance features (direct bf16 hi/lo)
    feat_kernel<<<MROWS, 256>>>(mask, embed, fh, fl);

    // iq / ik projections (1-pass, bf16-hi epilogue)
    mma_gemm_kernel<<<big_grid, 256, TC_SMEM>>>(ah, nullptr, wiqh, nullptr, biq, nullptr, iqh, nullptr, nullptr,
                                                MROWS, D_, D_, 0, 0, 0, 0, 1);
    mma_gemm_kernel<<<big_grid, 256, TC_SMEM>>>(fh, nullptr, wikh, nullptr, bik, nullptr, ikh, nullptr, nullptr,
                                                MROWS, D_, D_, 0, 0, 0, 0, 1);

    // gate: per-batch iq @ ik^T with fused sigmoid row-sum (atomics)
    zero_kernel<<<(MROWS+255)/256, 256>>>(gacc, MROWS);
    mma_gemm_kernel<<<dim3(4, 4, 8), 256, TC_SMEM>>>(iqh, nullptr, ikh, nullptr, nullptr, nullptr, nullptr,
                                                     nullptr, gacc,
                                                     512, 512, D_,
                                                     (long)512*D_, (long)512*D_, 0, 0, 3);

    // gated output projection: out = diag(1+gacc/512) * (attn @ Wo) + bo
    mma_gemm_kernel<<<big_grid, 256, TC_SMEM>>>(ah, al, woh, wol, bo, out, nullptr, gacc, nullptr,
                                                MROWS, D_, D_, 0, 0, 0, 1, 2);
}

// round 6
// speedup vs baseline: 3.5393x; 1.0027x over previous
#include <cuda_runtime.h>
#include <cuda_bf16.h>
#include <math.h>
#include <stdint.h>

// Problem constants
#define B_    8
#define N_    512
#define D_    1024
#define H_    16
#define HD_   64
#define NI_   4
#define G_    2
#define MROWS (B_*N_)      // 4096
#define SEQ   (NI_*N_)     // 2048
#define GH    (G_*H_)      // 32
#define D3    3072
#define SCALE 0.125f
#define S2    0.0078125f   // SCALE / H

// ---------------- scratch (device globals) -----------------------------------
static __device__ float g_qkvp[MROWS*D3];    // packed q|k|v projections
static __device__ float g_gacc[MROWS];
static __device__ float g_bqkv[D3];

// attention operand buffers: bf16 hi/lo, grouped layout [GH, SEQ, HD]
#define AELEMS (GH*SEQ*HD_)
static __device__ __align__(256) __nv_bfloat16 g_qhg[AELEMS], g_qlg[AELEMS];
static __device__ __align__(256) __nv_bfloat16 g_khg[AELEMS], g_klg[AELEMS];
static __device__ __align__(256) __nv_bfloat16 g_vhg[AELEMS], g_vlg[AELEMS];

// split-bf16 weight (transposed [N,K]) and activation buffers
static __device__ __align__(256) __nv_bfloat16 g_wqkvh[D3*D_], g_wqkvl[D3*D_];
static __device__ __align__(256) __nv_bfloat16 g_wiqh[D_*D_], g_wiql[D_*D_];
static __device__ __align__(256) __nv_bfloat16 g_wikh[D_*D_], g_wikl[D_*D_];
static __device__ __align__(256) __nv_bfloat16 g_woh[D_*D_], g_wol[D_*D_];
static __device__ __align__(256) __nv_bfloat16 g_xh[MROWS*D_],  g_xl[MROWS*D_];
static __device__ __align__(256) __nv_bfloat16 g_ah[MROWS*D_],  g_al[MROWS*D_];   // attn hi/lo
static __device__ __align__(256) __nv_bfloat16 g_fh[MROWS*D_],  g_fl[MROWS*D_];
static __device__ __align__(256) __nv_bfloat16 g_iqh[MROWS*D_];
static __device__ __align__(256) __nv_bfloat16 g_ikh[MROWS*D_];

// ---------------- PTX helpers --------------------------------------------------
__device__ __forceinline__ uint32_t smem_u32(const void* p) {
    uint32_t a;
    asm("{ .reg .u64 t; cvta.to.shared.u64 t, %1; cvt.u32.u64 %0, t; }"
        : "=r"(a) : "l"(p));
    return a;
}

#define LDSM4(r, addr) \
    asm volatile("ldmatrix.sync.aligned.m8n8.x4.shared.b16 {%0,%1,%2,%3}, [%4];" \
        : "=r"((r)[0]), "=r"((r)[1]), "=r"((r)[2]), "=r"((r)[3]) : "r"(addr))

#define LDSM4T(r, addr) \
    asm volatile("ldmatrix.sync.aligned.m8n8.x4.trans.shared.b16 {%0,%1,%2,%3}, [%4];" \
        : "=r"((r)[0]), "=r"((r)[1]), "=r"((r)[2]), "=r"((r)[3]) : "r"(addr))

#define MMA16816(d, a, bv0, bv1) \
    asm volatile("mma.sync.aligned.m16n8k16.row.col.f32.bf16.bf16.f32 " \
        "{%0,%1,%2,%3}, {%4,%5,%6,%7}, {%8,%9}, {%0,%1,%2,%3};" \
        : "+f"((d)[0]), "+f"((d)[1]), "+f"((d)[2]), "+f"((d)[3]) \
        : "r"((a)[0]), "r"((a)[1]), "r"((a)[2]), "r"((a)[3]), "r"(bv0), "r"(bv1))

#define CP_ASYNC16(dst, src) \
    asm volatile("cp.async.cg.shared.global [%0], [%1], 16;" \
        :: "r"(dst), "l"(__cvta_generic_to_global(src)) : "memory")
#define CP_COMMIT() asm volatile("cp.async.commit_group;" ::: "memory")
#define CP_WAIT(n)  asm volatile("cp.async.wait_group %0;" :: "n"(n) : "memory")

__device__ __forceinline__ uint32_t packbf(float a, float b) {
    uint32_t d;
    asm("cvt.rn.bf16x2.f32 %0, %1, %2;" : "=r"(d) : "f"(b), "f"(a));
    return d;
}
__device__ __forceinline__ float bflo(uint32_t v) { return __uint_as_float(v << 16); }
__device__ __forceinline__ float bfhi(uint32_t v) { return __uint_as_float(v & 0xffff0000u); }

// ---------------- HMMA split-bf16 GEMM, 3-stage cp.async pipeline -------------
// C[z] = A[z] @ B[z]^T + bias.
// three_pass: 1 -> AhBh + AhBl + AlBh ; 0 -> AhBh only.
// out_mode: 0 fp32 C+bias; 1 bf16-hi Cbf (+bias, blockIdx.z selects operand set 1/2);
//           2 fp32 gate-scaled; 3 sigmoid row-sum atomics into gout.
#define TC_SMEM_3P (3*65536)   // 196608
#define TC_SMEM_1P (3*32768)   //  98304
__global__ __launch_bounds__(256, 1)
void mma_gemm_kernel(const __nv_bfloat16* __restrict__ Ahp, const __nv_bfloat16* __restrict__ Alp,
                     const __nv_bfloat16* __restrict__ Bhp, const __nv_bfloat16* __restrict__ Blp,
                     const float* __restrict__ bias, float* __restrict__ C,
                     __nv_bfloat16* __restrict__ Cbf,
                     const float* __restrict__ grow, float* __restrict__ gout,
                     const __nv_bfloat16* __restrict__ Ahp2, const __nv_bfloat16* __restrict__ Bhp2,
                     const float* __restrict__ bias2, __nv_bfloat16* __restrict__ Cbf2,
                     int M, int N, int K, long sA, long sB, long sC,
                     int three_pass, int out_mode)
{
    extern __shared__ char smem[];
    uint32_t sb = smem_u32(smem);
    int tid = threadIdx.x, wid = tid >> 5, lane = tid & 31;
    int m0 = blockIdx.y * 128, n0 = blockIdx.x * 128;
    long zb = blockIdx.z;
    const __nv_bfloat16* Ah = Ahp + zb * sA;
    const __nv_bfloat16* Al = three_pass ? (Alp + zb * sA) : Ahp;
    const __nv_bfloat16* Bh = Bhp + zb * sB;
    const __nv_bfloat16* Bl = three_pass ? (Blp + zb * sB) : Bhp;
    if (out_mode == 1 && blockIdx.z == 1) {
        Ah = Ahp2; Bh = Bhp2; bias = bias2; Cbf = Cbf2;
    }

    const int nsteps = K / 64;
    const uint32_t SS   = three_pass ? 65536 : 32768;   // stage stride
    const uint32_t BOFF = three_pass ? 32768 : 16384;   // B tile offset in stage

    auto issue = [&](int step, int stage) {
        uint32_t stb = sb + stage * SS;
        int k0 = step * 64;
        if (three_pass) {
#pragma unroll
            for (int i = 0; i < 16; i++) {
                int c = i * 256 + tid;
                int tile = c >> 10;
                int w = c & 1023;
                int row = w >> 3, ch = w & 7;
                const __nv_bfloat16* src;
                int gr;
                if      (tile == 0) { src = Ah; gr = m0 + row; }
                else if (tile == 1) { src = Al; gr = m0 + row; }
                else if (tile == 2) { src = Bh; gr = n0 + row; }
                else                { src = Bl; gr = n0 + row; }
                const __nv_bfloat16* gp = src + (long)gr * K + k0 + ch * 8;
                uint32_t dst = stb + tile * 16384 + row * 128 + ((ch ^ (row & 7)) << 4);
                CP_ASYNC16(dst, gp);
            }
        } else {
#pragma unroll
            for (int i = 0; i < 8; i++) {
                int c = i * 256 + tid;
                int half = c >> 10;
                int w = c & 1023;
                int row = w >> 3, ch = w & 7;
                const __nv_bfloat16* src = half ? Bh : Ah;
                int gr = (half ? n0 : m0) + row;
                const __nv_bfloat16* gp = src + (long)gr * K + k0 + ch * 8;
                uint32_t dst = stb + half * 16384 + row * 128 + ((ch ^ (row & 7)) << 4);
                CP_ASYNC16(dst, gp);
            }
        }
        CP_COMMIT();
    };

    int mbase = (wid >> 2) * 64;
    int nbase = (wid & 3) * 32;

    float acc[4][4][4];
#pragma unroll
    for (int mt = 0; mt < 4; mt++)
#pragma unroll
        for (int nt = 0; nt < 4; nt++)
#pragma unroll
            for (int e = 0; e < 4; e++) acc[mt][nt][e] = 0.f;

    issue(0, 0);
    if (nsteps > 1) issue(1, 1);
    if (nsteps > 2) issue(2, 2);

    for (int step = 0; step < nsteps; step++) {
        int rem = nsteps - 1 - step;
        if (rem >= 2)      { CP_WAIT(2); }
        else if (rem == 1) { CP_WAIT(1); }
        else               { CP_WAIT(0); }
        __syncthreads();

        uint32_t stb = sb + (uint32_t)(step % 3) * SS;
#pragma unroll
        for (int k16 = 0; k16 < 4; k16++) {
            uint32_t ahf[4][4], alf[4][4], bhf[2][4], blf[2][4];
            int arow = lane & 15;
            int ach = 2 * k16 + (lane >> 4);
#pragma unroll
            for (int mt = 0; mt < 4; mt++) {
                int row = mbase + mt * 16 + arow;
                uint32_t ad = stb + row * 128 + ((ach ^ (row & 7)) << 4);
                LDSM4(ahf[mt], ad);
                if (three_pass) LDSM4(alf[mt], ad + 16384);
            }
            int brow = (lane & 7) + ((lane >> 4) & 1) * 8;
            int bch = 2 * k16 + ((lane >> 3) & 1);
#pragma unroll
            for (int j = 0; j < 2; j++) {
                int row = nbase + j * 16 + brow;
                uint32_t bd = stb + BOFF + row * 128 + ((bch ^ (row & 7)) << 4);
                LDSM4(bhf[j], bd);
                if (three_pass) LDSM4(blf[j], bd + 16384);
            }
#pragma unroll
            for (int mt = 0; mt < 4; mt++)
#pragma unroll
                for (int nt = 0; nt < 4; nt++) {
                    int j = nt >> 1, p = (nt & 1) * 2;
                    MMA16816(acc[mt][nt], ahf[mt], bhf[j][p], bhf[j][p+1]);
                }
            if (three_pass) {
#pragma unroll
                for (int mt = 0; mt < 4; mt++)
#pragma unroll
                    for (int nt = 0; nt < 4; nt++) {
                        int j = nt >> 1, p = (nt & 1) * 2;
                        MMA16816(acc[mt][nt], ahf[mt], blf[j][p], blf[j][p+1]);
                    }
#pragma unroll
                for (int mt = 0; mt < 4; mt++)
#pragma unroll
                    for (int nt = 0; nt < 4; nt++) {
                        int j = nt >> 1, p = (nt & 1) * 2;
                        MMA16816(acc[mt][nt], alf[mt], bhf[j][p], bhf[j][p+1]);
                    }
            }
        }
        __syncthreads();
        if (step + 3 < nsteps) issue(step + 3, step % 3);
    }

    // ------------------------------ epilogues ---------------------------------
    if (out_mode == 3) {
#pragma unroll
        for (int mt = 0; mt < 4; mt++) {
            int r0 = m0 + mbase + mt * 16 + (lane >> 2);
            float ps0 = 0.f, ps1 = 0.f;
#pragma unroll
            for (int nt = 0; nt < 4; nt++) {
                ps0 += 1.0f / (1.0f + __expf(-acc[mt][nt][0] * S2));
                ps0 += 1.0f / (1.0f + __expf(-acc[mt][nt][1] * S2));
                ps1 += 1.0f / (1.0f + __expf(-acc[mt][nt][2] * S2));
                ps1 += 1.0f / (1.0f + __expf(-acc[mt][nt][3] * S2));
            }
            ps0 += __shfl_xor_sync(0xffffffffu, ps0, 1, 4);
            ps0 += __shfl_xor_sync(0xffffffffu, ps0, 2, 4);
            ps1 += __shfl_xor_sync(0xffffffffu, ps1, 1, 4);
            ps1 += __shfl_xor_sync(0xffffffffu, ps1, 2, 4);
            if ((lane & 3) == 0) {
                atomicAdd(&gout[zb * 512 + r0], ps0);
                atomicAdd(&gout[zb * 512 + r0 + 8], ps1);
            }
        }
        return;
    }

#pragma unroll
    for (int mt = 0; mt < 4; mt++) {
        int r0 = m0 + mbase + mt * 16 + (lane >> 2);
        float g0 = 1.f, g1 = 1.f;
        if (out_mode == 2) {
            g0 = 1.0f + grow[r0] * (1.0f/512.0f);
            g1 = 1.0f + grow[r0 + 8] * (1.0f/512.0f);
        }
#pragma unroll
        for (int nt = 0; nt < 4; nt++) {
            int c = n0 + nbase + nt * 8 + 2 * (lane & 3);
            float b0 = 0.f, b1 = 0.f;
            if (bias) { b0 = bias[c]; b1 = bias[c + 1]; }
            float v00 = acc[mt][nt][0] * g0 + b0, v01 = acc[mt][nt][1] * g0 + b1;
            float v10 = acc[mt][nt][2] * g1 + b0, v11 = acc[mt][nt][3] * g1 + b1;
            if (out_mode == 1) {
                *(uint32_t*)&Cbf[(long)r0 * N + c]       = packbf(v00, v01);
                *(uint32_t*)&Cbf[(long)(r0 + 8) * N + c] = packbf(v10, v11);
            } else {
                float* Cc = C + zb * sC;
                float2 w0; w0.x = v00; w0.y = v01;
                *(float2*)&Cc[(long)r0 * N + c] = w0;
                float2 w1; w1.x = v10; w1.y = v11;
                *(float2*)&Cc[(long)(r0 + 8) * N + c] = w1;
            }
        }
    }
}

// ---------------- weight transpose + split to bf16 (64x64 tiles) -------------
__global__ __launch_bounds__(256) void wt_split_kernel(
    const float* __restrict__ W, __nv_bfloat16* __restrict__ Th, __nv_bfloat16* __restrict__ Tl)
{
    __shared__ float t[64][65];
    int n0 = blockIdx.x * 64, k0 = blockIdx.y * 64;
    int tid = threadIdx.x;
#pragma unroll
    for (int it = 0; it < 4; it++) {
        int row = (tid >> 4) + it * 16;
        int c4 = (tid & 15) * 4;
        float4 v = *(const float4*)&W[(long)(k0 + row) * D_ + n0 + c4];
        t[row][c4+0] = v.x; t[row][c4+1] = v.y; t[row][c4+2] = v.z; t[row][c4+3] = v.w;
    }
    __syncthreads();
    int n = tid >> 2, kc = (tid & 3) * 16;
    uint32_t hb[8], lb[8];
#pragma unroll
    for (int j = 0; j < 16; j += 2) {
        float f0 = t[kc + j][n], f1 = t[kc + j + 1][n];
        uint32_t h = packbf(f0, f1);
        hb[j >> 1] = h;
        lb[j >> 1] = packbf(f0 - bflo(h), f1 - bfhi(h));
    }
    long obase = (long)(n0 + n) * D_ + k0 + kc;
    *(uint4*)&Th[obase]     = make_uint4(hb[0], hb[1], hb[2], hb[3]);
    *(uint4*)&Th[obase + 8] = make_uint4(hb[4], hb[5], hb[6], hb[7]);
    *(uint4*)&Tl[obase]     = make_uint4(lb[0], lb[1], lb[2], lb[3]);
    *(uint4*)&Tl[obase + 8] = make_uint4(lb[4], lb[5], lb[6], lb[7]);
}

// ---------------- bias concat (bq|bk|bv) --------------------------------------
__global__ void bias3_kernel(const float* __restrict__ a, const float* __restrict__ b,
                             const float* __restrict__ c, float* __restrict__ o)
{
    int i = blockIdx.x * 256 + threadIdx.x;
    if (i < 1024)       o[i] = a[i];
    else if (i < 2048)  o[i] = b[i - 1024];
    else if (i < 3072)  o[i] = c[i - 2048];
}

// ---------------- activation split ---------------------------------------------
__global__ __launch_bounds__(256) void split_kernel(
    const float* __restrict__ src, __nv_bfloat16* __restrict__ h,
    __nv_bfloat16* __restrict__ l, int n4)
{
    int i = blockIdx.x * 256 + threadIdx.x;
    if (i >= n4) return;
    float4 f = ((const float4*)src)[i];
    uint32_t h0 = packbf(f.x, f.y), h1 = packbf(f.z, f.w);
    ((uint32_t*)h)[i*2+0] = h0;
    ((uint32_t*)h)[i*2+1] = h1;
    ((uint32_t*)l)[i*2+0] = packbf(f.x - bflo(h0), f.y - bfhi(h0));
    ((uint32_t*)l)[i*2+1] = packbf(f.z - bflo(h1), f.w - bfhi(h1));
}

// ------- RMS-norm (q,k) + split to bf16 hi/lo, scatter into [GH, SEQ, HD] ----
// reads packed qkv [MROWS, 3072]
__global__ __launch_bounds__(256) void rms_scatter_kernel(
    const float* __restrict__ qkv,
    const float* __restrict__ qw, const float* __restrict__ kw,
    __nv_bfloat16* __restrict__ qh, __nv_bfloat16* __restrict__ ql,
    __nv_bfloat16* __restrict__ kh, __nv_bfloat16* __restrict__ kl,
    __nv_bfloat16* __restrict__ vh, __nv_bfloat16* __restrict__ vl)
{
    int wid  = (blockIdx.x * 256 + threadIdx.x) >> 5;
    int lane = threadIdx.x & 31;
    int h  = wid & 15;
    int bn = wid >> 4;
    int b  = bn >> 9;
    long ibase = (long)bn * D3 + h * HD_;
    int g = b >> 2, inst = b & 3;
    int n = bn & 511;
    long obase = (((long)(g*16 + h)) * SEQ + inst*512 + n) * HD_;

    auto emit = [&](float v, __nv_bfloat16* ph, __nv_bfloat16* pl, long off) {
        __nv_bfloat16 hb = __float2bfloat16(v);
        ph[off] = hb;
        pl[off] = __float2bfloat16(v - __bfloat162float(hb));
    };
    {
        float v0 = qkv[ibase + lane], v1 = qkv[ibase + lane + 32];
        float ss = v0*v0 + v1*v1;
#pragma unroll
        for (int off = 16; off; off >>= 1) ss += __shfl_xor_sync(0xffffffffu, ss, off);
        float sc = rsqrtf(ss * (1.0f/64.0f) + 1e-6f) * SCALE;
        emit(v0 * sc * qw[lane],      qh, ql, obase + lane);
        emit(v1 * sc * qw[lane + 32], qh, ql, obase + lane + 32);
    }
    {
        float v0 = qkv[ibase + 1024 + lane], v1 = qkv[ibase + 1024 + lane + 32];
        float ss = v0*v0 + v1*v1;
#pragma unroll
        for (int off = 16; off; off >>= 1) ss += __shfl_xor_sync(0xffffffffu, ss, off);
        float sc = rsqrtf(ss * (1.0f/64.0f) + 1e-6f);
        emit(v0 * sc * kw[lane],      kh, kl, obase + lane);
        emit(v1 * sc * kw[lane + 32], kh, kl, obase + lane + 32);
    }
    emit(qkv[ibase + 2048 + lane],      vh, vl, obase + lane);
    emit(qkv[ibase + 2048 + lane + 32], vh, vl, obase + lane + 32);
}

// ---------------- flash attention via mma.sync (split-bf16 3-pass) -----------
#define FL_SMEM (2*65536 + 32768)
__global__ __launch_bounds__(256, 1)
void flash_mma_kernel(const __nv_bfloat16* __restrict__ Qh_, const __nv_bfloat16* __restrict__ Ql_,
                      const __nv_bfloat16* __restrict__ Kh_, const __nv_bfloat16* __restrict__ Kl_,
                      const __nv_bfloat16* __restrict__ Vh_, const __nv_bfloat16* __restrict__ Vl_,
                      __nv_bfloat16* __restrict__ Oh, __nv_bfloat16* __restrict__ Ol)
{
    extern __shared__ char smem[];
    uint32_t sb = smem_u32(smem);
    int tid = threadIdx.x, wid = tid >> 5, lane = tid & 31;
    int qt = blockIdx.x, gh = blockIdx.y;
    long ghoff = (long)gh * SEQ * HD_;
    const __nv_bfloat16* Qh = Qh_ + ghoff + (long)qt * 128 * HD_;
    const __nv_bfloat16* Ql = Ql_ + ghoff + (long)qt * 128 * HD_;
    const __nv_bfloat16* Kh = Kh_ + ghoff;
    const __nv_bfloat16* Kl = Kl_ + ghoff;
    const __nv_bfloat16* Vh = Vh_ + ghoff;
    const __nv_bfloat16* Vl = Vl_ + ghoff;

    const uint32_t QOFF = 131072;

    {
#pragma unroll
        for (int i = 0; i < 8; i++) {
            int c = i * 256 + tid;
            int arr = c >> 10, w = c & 1023, row = w >> 3, ch = w & 7;
            const __nv_bfloat16* src = (arr ? Ql : Qh) + (long)row * 64 + ch * 8;
            uint32_t dst = sb + QOFF + arr * 16384 + row * 128 + ((ch ^ (row & 7)) << 4);
            CP_ASYNC16(dst, src);
        }
        CP_COMMIT();
    }

    auto issueKV = [&](int it, int stage) {
        uint32_t stb = sb + stage * 65536;
#pragma unroll
        for (int i = 0; i < 16; i++) {
            int c = i * 256 + tid;
            int arr = c >> 10, w = c & 1023, row = w >> 3, ch = w & 7;
            const __nv_bfloat16* src;
            if      (arr == 0) src = Kh;
            else if (arr == 1) src = Kl;
            else if (arr == 2) src = Vh;
            else               src = Vl;
            src += (long)(it * 128 + row) * 64 + ch * 8;
            uint32_t dst = stb + arr * 16384 + row * 128 + ((ch ^ (row & 7)) << 4);
            CP_ASYNC16(dst, src);
        }
        CP_COMMIT();
    };

    issueKV(0, 0);
    issueKV(1, 1);
    CP_WAIT(1);
    __syncthreads();

    uint32_t qhf[4][4], qlf[4][4];
    {
        int arow = lane & 15;
#pragma unroll
        for (int kt = 0; kt < 4; kt++) {
            int row = wid * 16 + arow;
            int ach = 2 * kt + (lane >> 4);
            uint32_t ad = sb + QOFF + row * 128 + ((ach ^ (row & 7)) << 4);
            LDSM4(qhf[kt], ad);
            LDSM4(qlf[kt], ad + 16384);
        }
    }

    float o[8][4];
#pragma unroll
    for (int nt = 0; nt < 8; nt++)
#pragma unroll
        for (int e = 0; e < 4; e++) o[nt][e] = 0.f;
    float m0 = -1e30f, m1 = -1e30f, lp0 = 0.f, lp1 = 0.f;

    for (int it = 0; it < 16; it++) {
        if (it > 0) {
            if (it < 15) { CP_WAIT(1); } else { CP_WAIT(0); }
            __syncthreads();
        }
        uint32_t stb = sb + (it & 1) * 65536;

        float s[16][4];
#pragma unroll
        for (int t = 0; t < 16; t++)
#pragma unroll
            for (int e = 0; e < 4; e++) s[t][e] = 0.f;

        int brow = (lane & 7) + ((lane >> 4) & 1) * 8;
#pragma unroll
        for (int kt = 0; kt < 4; kt++) {
            int bch = 2 * kt + ((lane >> 3) & 1);
#pragma unroll
            for (int jp = 0; jp < 4; jp++) {
                uint32_t khf[2][4], klf[2][4];
#pragma unroll
                for (int j = 0; j < 2; j++) {
                    int row = (2 * jp + j) * 16 + brow;
                    uint32_t bd = stb + row * 128 + ((bch ^ (row & 7)) << 4);
                    LDSM4(khf[j], bd);
                    LDSM4(klf[j], bd + 16384);
                }
                int t0 = 4 * jp;
                MMA16816(s[t0+0], qhf[kt], khf[0][0], khf[0][1]);
                MMA16816(s[t0+1], qhf[kt], khf[0][2], khf[0][3]);
                MMA16816(s[t0+2], qhf[kt], khf[1][0], khf[1][1]);
                MMA16816(s[t0+3], qhf[kt], khf[1][2], khf[1][3]);
                MMA16816(s[t0+0], qhf[kt], klf[0][0], klf[0][1]);
                MMA16816(s[t0+1], qhf[kt], klf[0][2], klf[0][3]);
                MMA16816(s[t0+2], qhf[kt], klf[1][0], klf[1][1]);
                MMA16816(s[t0+3], qhf[kt], klf[1][2], klf[1][3]);
                MMA16816(s[t0+0], qlf[kt], khf[0][0], khf[0][1]);
                MMA16816(s[t0+1], qlf[kt], khf[0][2], khf[0][3]);
                MMA16816(s[t0+2], qlf[kt], khf[1][0], khf[1][1]);
                MMA16816(s[t0+3], qlf[kt], khf[1][2], khf[1][3]);
            }
        }

        float t0 = -1e30f, t1 = -1e30f;
#pragma unroll
        for (int t = 0; t < 16; t++) {
            t0 = fmaxf(t0, fmaxf(s[t][0], s[t][1]));
            t1 = fmaxf(t1, fmaxf(s[t][2], s[t][3]));
        }
        t0 = fmaxf(t0, __shfl_xor_sync(0xffffffffu, t0, 1, 4));
        t0 = fmaxf(t0, __shfl_xor_sync(0xffffffffu, t0, 2, 4));
        t1 = fmaxf(t1, __shfl_xor_sync(0xffffffffu, t1, 1, 4));
        t1 = fmaxf(t1, __shfl_xor_sync(0xffffffffu, t1, 2, 4));
        float mn0 = fmaxf(m0, t0), mn1 = fmaxf(m1, t1);
        float c0 = __expf(m0 - mn0), c1 = __expf(m1 - mn1);
        m0 = mn0; m1 = mn1;
        lp0 *= c0; lp1 *= c1;
#pragma unroll
        for (int nt = 0; nt < 8; nt++) {
            o[nt][0] *= c0; o[nt][1] *= c0;
            o[nt][2] *= c1; o[nt][3] *= c1;
        }
#pragma unroll
        for (int t = 0; t < 16; t++) {
            s[t][0] = __expf(s[t][0] - m0);
            s[t][1] = __expf(s[t][1] - m0);
            s[t][2] = __expf(s[t][2] - m1);
            s[t][3] = __expf(s[t][3] - m1);
            lp0 += s[t][0] + s[t][1];
            lp1 += s[t][2] + s[t][3];
        }

        int vrow = lane & 15;
#pragma unroll
        for (int kt = 0; kt < 8; kt++) {
            uint32_t pha[4], pla[4];
#pragma unroll
            for (int q = 0; q < 2; q++) {
                float a0 = s[2*kt + q][0], a1 = s[2*kt + q][1];
                float a2 = s[2*kt + q][2], a3 = s[2*kt + q][3];
                uint32_t h0 = packbf(a0, a1);
                uint32_t h1 = packbf(a2, a3);
                pha[2*q]   = h0;
                pha[2*q+1] = h1;
                pla[2*q]   = packbf(a0 - bflo(h0), a1 - bfhi(h0));
                pla[2*q+1] = packbf(a2 - bflo(h1), a3 - bfhi(h1));
            }
            int row = kt * 16 + vrow;
#pragma unroll
            for (int np = 0; np < 2; np++) {
                uint32_t vhf[2][4], vlf[2][4];
#pragma unroll
                for (int j = 0; j < 2; j++) {
                    int ch = 2 * (2 * np + j) + (lane >> 4);
                    uint32_t vd = stb + 32768 + row * 128 + ((ch ^ (row & 7)) << 4);
                    LDSM4T(vhf[j], vd);
                    LDSM4T(vlf[j], vd + 16384);
                }
                int ob = 4 * np;
                MMA16816(o[ob+0], pha, vhf[0][0], vhf[0][1]);
                MMA16816(o[ob+1], pha, vhf[0][2], vhf[0][3]);
                MMA16816(o[ob+2], pha, vhf[1][0], vhf[1][1]);
                MMA16816(o[ob+3], pha, vhf[1][2], vhf[1][3]);
                MMA16816(o[ob+0], pha, vlf[0][0], vlf[0][1]);
                MMA16816(o[ob+1], pha, vlf[0][2], vlf[0][3]);
                MMA16816(o[ob+2], pha, vlf[1][0], vlf[1][1]);
                MMA16816(o[ob+3], pha, vlf[1][2], vlf[1][3]);
                MMA16816(o[ob+0], pla, vhf[0][0], vhf[0][1]);
                MMA16816(o[ob+1], pla, vhf[0][2], vhf[0][3]);
                MMA16816(o[ob+2], pla, vhf[1][0], vhf[1][1]);
                MMA16816(o[ob+3], pla, vhf[1][2], vhf[1][3]);
            }
        }

        __syncthreads();
        if (it + 2 < 16) issueKV(it + 2, it & 1);
    }

    lp0 += __shfl_xor_sync(0xffffffffu, lp0, 1, 4);
    lp0 += __shfl_xor_sync(0xffffffffu, lp0, 2, 4);
    lp1 += __shfl_xor_sync(0xffffffffu, lp1, 1, 4);
    lp1 += __shfl_xor_sync(0xffffffffu, lp1, 2, 4);
    float inv0 = 1.0f / lp0, inv1 = 1.0f / lp1;

    int g = gh >> 4, h = gh & 15;
#pragma unroll
    for (int e = 0; e < 2; e++) {
        int r = qt * 128 + wid * 16 + (lane >> 2) + 8 * e;
        int inst = r >> 9, n = r & 511;
        int b = g * 4 + inst;
        float inv = e ? inv1 : inv0;
        long base = ((long)(b * 512 + n)) * D_ + h * HD_;
#pragma unroll
        for (int nt = 0; nt < 8; nt++) {
            float v0 = o[nt][2*e] * inv, v1 = o[nt][2*e+1] * inv;
            uint32_t hp = packbf(v0, v1);
            uint32_t lp = packbf(v0 - bflo(hp), v1 - bfhi(hp));
            long idx = base + nt * 8 + 2 * (lane & 3);
            *(uint32_t*)&Oh[idx] = hp;
            *(uint32_t*)&Ol[idx] = lp;
        }
    }
}

// ---------------- instance feature -> bf16 hi/lo ------------------------------
__global__ __launch_bounds__(256) void feat_kernel(
    const float* __restrict__ mask, const float* __restrict__ embed,
    __nv_bfloat16* __restrict__ fh, __nv_bfloat16* __restrict__ fl)
{
    int row = blockIdx.x;
    float m0 = mask[row*4+0], m1 = mask[row*4+1];
    float m2 = mask[row*4+2], m3 = mask[row*4+3];
    for (int c = threadIdx.x * 2; c < D_; c += 512) {
        float f0 = m0*embed[c]   + m1*embed[D_ + c]   + m2*embed[2*D_ + c]   + m3*embed[3*D_ + c];
        float f1 = m0*embed[c+1] + m1*embed[D_ + c+1] + m2*embed[2*D_ + c+1] + m3*embed[3*D_ + c+1];
        uint32_t h = packbf(f0, f1);
        *(uint32_t*)&fh[(long)row*D_ + c] = h;
        *(uint32_t*)&fl[(long)row*D_ + c] = packbf(f0 - bflo(h), f1 - bfhi(h));
    }
}

__global__ void zero_kernel(float* __restrict__ p, int n)
{
    int i = blockIdx.x * blockDim.x + threadIdx.x;
    if (i < n) p[i] = 0.f;
}

// ------------------------------- launch --------------------------------------
extern "C" void kernel_launch(void* const* d_in, const int* in_sizes, int n_in,
                              void* d_out, int out_size)
{
    const float* x     = (const float*)d_in[0];
    const float* mask  = (const float*)d_in[1];
    const float* Wq    = (const float*)d_in[2];
    const float* bq    = (const float*)d_in[3];
    const float* Wk    = (const float*)d_in[4];
    const float* bk    = (const float*)d_in[5];
    const float* Wv    = (const float*)d_in[6];
    const float* bv    = (const float*)d_in[7];
    const float* Wo    = (const float*)d_in[8];
    const float* bo    = (const float*)d_in[9];
    const float* Wiq   = (const float*)d_in[10];
    const float* biq   = (const float*)d_in[11];
    const float* Wik   = (const float*)d_in[12];
    const float* bik   = (const float*)d_in[13];
    const float* embed = (const float*)d_in[14];
    const float* qw    = (const float*)d_in[15];
    const float* kw    = (const float*)d_in[16];
    float* out = (float*)d_out;

    float *qkvp,*gacc,*bqkv;
    cudaGetSymbolAddress((void**)&qkvp, g_qkvp);
    cudaGetSymbolAddress((void**)&gacc, g_gacc);
    cudaGetSymbolAddress((void**)&bqkv, g_bqkv);

    __nv_bfloat16 *qhg,*qlg,*khg,*klg,*vhg,*vlg;
    cudaGetSymbolAddress((void**)&qhg, g_qhg);   cudaGetSymbolAddress((void**)&qlg, g_qlg);
    cudaGetSymbolAddress((void**)&khg, g_khg);   cudaGetSymbolAddress((void**)&klg, g_klg);
    cudaGetSymbolAddress((void**)&vhg, g_vhg);   cudaGetSymbolAddress((void**)&vlg, g_vlg);

    __nv_bfloat16 *wqkvh,*wqkvl,*wiqh,*wiql,*wikh,*wikl,*woh,*wol;
    __nv_bfloat16 *xh,*xl,*ah,*al,*fh,*fl,*iqh,*ikh;
    cudaGetSymbolAddress((void**)&wqkvh, g_wqkvh); cudaGetSymbolAddress((void**)&wqkvl, g_wqkvl);
    cudaGetSymbolAddress((void**)&wiqh, g_wiqh);   cudaGetSymbolAddress((void**)&wiql, g_wiql);
    cudaGetSymbolAddress((void**)&wikh, g_wikh);   cudaGetSymbolAddress((void**)&wikl, g_wikl);
    cudaGetSymbolAddress((void**)&woh, g_woh);     cudaGetSymbolAddress((void**)&wol, g_wol);
    cudaGetSymbolAddress((void**)&xh, g_xh);       cudaGetSymbolAddress((void**)&xl, g_xl);
    cudaGetSymbolAddress((void**)&ah, g_ah);       cudaGetSymbolAddress((void**)&al, g_al);
    cudaGetSymbolAddress((void**)&fh, g_fh);       cudaGetSymbolAddress((void**)&fl, g_fl);
    cudaGetSymbolAddress((void**)&iqh, g_iqh);     cudaGetSymbolAddress((void**)&ikh, g_ikh);

    cudaFuncSetAttribute((const void*)mma_gemm_kernel,
                         cudaFuncAttributeMaxDynamicSharedMemorySize, TC_SMEM_3P);
    cudaFuncSetAttribute((const void*)flash_mma_kernel,
                         cudaFuncAttributeMaxDynamicSharedMemorySize, FL_SMEM);

    dim3 wtg(16, 16);
    const int N4 = MROWS * D_ / 4;
    const int SPLIT_BLOCKS = (N4 + 255) / 256;
    dim3 big_grid(D_/128, MROWS/128, 1);     // (8, 32)
    dim3 qkv_grid(D3/128, MROWS/128, 1);     // (24, 32)

    // weight prep: Wq/Wk/Wv into concatenated [3072,1024] buffers
    wt_split_kernel<<<wtg, 256>>>(Wq,  wqkvh,             wqkvl);
    wt_split_kernel<<<wtg, 256>>>(Wk,  wqkvh + 1024*1024, wqkvl + 1024*1024);
    wt_split_kernel<<<wtg, 256>>>(Wv,  wqkvh + 2048*1024, wqkvl + 2048*1024);
    wt_split_kernel<<<wtg, 256>>>(Wiq, wiqh, wiql);
    wt_split_kernel<<<wtg, 256>>>(Wik, wikh, wikl);
    wt_split_kernel<<<wtg, 256>>>(Wo,  woh,  wol);
    bias3_kernel<<<12, 256>>>(bq, bk, bv, bqkv);

    // x split + fused QKV projection (3-pass, N=3072)
    split_kernel<<<SPLIT_BLOCKS, 256>>>(x, xh, xl, N4);
    mma_gemm_kernel<<<qkv_grid, 256, TC_SMEM_3P>>>(
        xh, xl, wqkvh, wqkvl, bqkv, qkvp, nullptr, nullptr, nullptr,
        nullptr, nullptr, nullptr, nullptr,
        MROWS, D3, D_, 0, 0, 0, 1, 0);

    // per-head RMS norm + split/scatter; attention (writes ah/al directly)
    rms_scatter_kernel<<<(MROWS*H_)/8, 256>>>(qkvp, qw, kw,
                                              qhg, qlg, khg, klg, vhg, vlg);
    flash_mma_kernel<<<dim3(SEQ/128, GH), 256, FL_SMEM>>>(qhg, qlg, khg, klg, vhg, vlg, ah, al);

    // instance features
    feat_kernel<<<MROWS, 256>>>(mask, embed, fh, fl);

    // iq & ik projections fused in one launch (z selects operand set)
    mma_gemm_kernel<<<dim3(8, 32, 2), 256, TC_SMEM_1P>>>(
        ah, nullptr, wiqh, nullptr, biq, nullptr, iqh, nullptr, nullptr,
        fh, wikh, bik, ikh,
        MROWS, D_, D_, 0, 0, 0, 0, 1);

    // gate: per-batch iq @ ik^T with fused sigmoid row-sum (atomics)
    zero_kernel<<<(MROWS+255)/256, 256>>>(gacc, MROWS);
    mma_gemm_kernel<<<dim3(4, 4, 8), 256, TC_SMEM_1P>>>(
        iqh, nullptr, ikh, nullptr, nullptr, nullptr, nullptr, nullptr, gacc,
        nullptr, nullptr, nullptr, nullptr,
        512, 512, D_, (long)512*D_, (long)512*D_, 0, 0, 3);

    // gated output projection: out = diag(1+gacc/512) * (attn @ Wo) + bo
    mma_gemm_kernel<<<big_grid, 256, TC_SMEM_3P>>>(
        ah, al, woh, wol, bo, out, nullptr, gacc, nullptr,
        nullptr, nullptr, nullptr, nullptr,
        MROWS, D_, D_, 0, 0, 0, 1, 2);
}